// round 2
// baseline (speedup 1.0000x reference)
#include <cuda_runtime.h>
#include <math.h>
#include <stdint.h>

// ---------------------------------------------------------------------------
// TinyMoE: out = residual + shared_swiglu(x) @ Wd_s + sum_topk w_k * expert_k(x)
// T=4096 tokens, H=I=1024, E=8 experts, top-2 routing.
// Strategy: route first, compute only selected (token,expert) pairs.
// fp32 end-to-end (rel_err ~1e-6), packed f32x2 FMA microkernel.
// ---------------------------------------------------------------------------

#define T_TOK   4096
#define HD      1024
#define ID      1024
#define NE      8
#define PER_E   4096   // max tokens per expert (each token selects an expert at most once)

using ull = unsigned long long;

// ---- device scratch (allocation-free rule: static __device__ globals) ----
__device__ int   g_cnt[NE];
__device__ int   g_tok[NE][PER_E];
__device__ float g_wt [NE][PER_E];
__device__ float g_hid_s[(size_t)T_TOK * ID];            // shared-expert hidden
__device__ float g_hid_r[(size_t)NE * PER_E * ID];       // routed hidden (per expert, compacted)

// ---- packed f32x2 helpers (sm_103a) ----
__device__ __forceinline__ ull pack2(float lo, float hi) {
    ull r;
    asm("mov.b64 %0, {%1,%2};" : "=l"(r) : "r"(__float_as_uint(lo)), "r"(__float_as_uint(hi)));
    return r;
}
__device__ __forceinline__ void unpack2(ull v, float& lo, float& hi) {
    unsigned a, b;
    asm("mov.b64 {%0,%1}, %2;" : "=r"(a), "=r"(b) : "l"(v));
    lo = __uint_as_float(a); hi = __uint_as_float(b);
}
__device__ __forceinline__ ull fma2(ull a, ull b, ull c) {
    ull d;
    asm("fma.rn.f32x2 %0, %1, %2, %3;" : "=l"(d) : "l"(a), "l"(b), "l"(c));
    return d;
}

// ---------------------------------------------------------------------------
// init: zero per-expert counters
// ---------------------------------------------------------------------------
__global__ void k_init() {
    if (threadIdx.x < NE) g_cnt[threadIdx.x] = 0;
}

// ---------------------------------------------------------------------------
// router: one warp per token. 8 dot products over H, softmax, greedy top-2.
// Greedy argmax with strict '>' matches jax.lax.top_k tie-breaking (lowest idx).
// ---------------------------------------------------------------------------
__global__ void k_router(const float* __restrict__ X, const float* __restrict__ RW) {
    const int gwarp = (blockIdx.x * blockDim.x + threadIdx.x) >> 5;
    const int lane  = threadIdx.x & 31;
    if (gwarp >= T_TOK) return;

    const float* xr = X + (size_t)gwarp * HD;
    float acc[NE];
#pragma unroll
    for (int e = 0; e < NE; e++) acc[e] = 0.f;

    for (int h = lane; h < HD; h += 32) {
        const float xv = xr[h];
#pragma unroll
        for (int e = 0; e < NE; e++) acc[e] += xv * RW[e * HD + h];
    }
#pragma unroll
    for (int e = 0; e < NE; e++)
#pragma unroll
        for (int off = 16; off > 0; off >>= 1)
            acc[e] += __shfl_down_sync(0xffffffffu, acc[e], off);

    if (lane == 0) {
        float m = acc[0];
#pragma unroll
        for (int e = 1; e < NE; e++) m = fmaxf(m, acc[e]);
        float p[NE], s = 0.f;
#pragma unroll
        for (int e = 0; e < NE; e++) { p[e] = expf(acc[e] - m); s += p[e]; }
        const float inv = 1.f / s;
#pragma unroll
        for (int e = 0; e < NE; e++) p[e] *= inv;

        int   i1 = 0; float b1 = p[0];
#pragma unroll
        for (int e = 1; e < NE; e++) if (p[e] > b1) { b1 = p[e]; i1 = e; }
        int   i2 = -1; float b2 = -1.f;
#pragma unroll
        for (int e = 0; e < NE; e++) if (e != i1 && p[e] > b2) { b2 = p[e]; i2 = e; }

        int pos = atomicAdd(&g_cnt[i1], 1);
        g_tok[i1][pos] = gwarp; g_wt[i1][pos] = b1;  // routed_scaling_factor = 1
        pos = atomicAdd(&g_cnt[i2], 1);
        g_tok[i2][pos] = gwarp; g_wt[i2][pos] = b2;
    }
}

// ---------------------------------------------------------------------------
// Fused gate+up GEMM + SwiGLU: H = sigmoid(X@Wg) * (X@Wu)
// Tile 128x128, BK=8, 256 threads, 8x8 per thread, dual f32x2 accumulators.
// GATHER=true: rows gathered via g_tok[e], weights offset by expert,
//              output compacted into g_hid_r[e].
// ---------------------------------------------------------------------------
template<bool GATHER>
__global__ void __launch_bounds__(256, 1)
k_gateup(const float* __restrict__ X,
         const float* __restrict__ Wg_all,
         const float* __restrict__ Wu_all)
{
    constexpr int BM = 128, BN = 128, BK = 8;
    __shared__ float As[BK][BM];
    __shared__ float Bg[BK][BN];
    __shared__ float Bu[BK][BN];

    const int bn = blockIdx.x * BN;
    const int bm = blockIdx.y * BM;

    int nrows;
    const int*   toks = nullptr;
    const float *Wg, *Wu;
    float* Hout;
    if (GATHER) {
        const int e = blockIdx.z;
        nrows = g_cnt[e];
        if (bm >= nrows) return;
        toks = g_tok[e];
        Wg   = Wg_all + (size_t)e * HD * ID;
        Wu   = Wu_all + (size_t)e * HD * ID;
        Hout = g_hid_r + (size_t)e * PER_E * ID;
    } else {
        nrows = T_TOK;
        Wg = Wg_all; Wu = Wu_all;
        Hout = g_hid_s;
    }

    const int tid  = threadIdx.x;
    const int arow = tid >> 1,  acol = (tid & 1) * 4;
    const int brow = tid >> 5,  bcol = (tid & 31) * 4;
    const int tx   = tid & 15,  ty   = tid >> 4;

    int agrow;
    if (GATHER) {
        const int slot = bm + arow;
        agrow = (slot < nrows) ? toks[slot] : -1;
    } else {
        agrow = bm + arow;
    }

    ull accG[8][4], accU[8][4];
#pragma unroll
    for (int i = 0; i < 8; i++)
#pragma unroll
        for (int j = 0; j < 4; j++) { accG[i][j] = 0ull; accU[i][j] = 0ull; }

    for (int k0 = 0; k0 < HD; k0 += BK) {
        float4 av = make_float4(0.f, 0.f, 0.f, 0.f);
        if (agrow >= 0)
            av = *reinterpret_cast<const float4*>(X + (size_t)agrow * HD + k0 + acol);
        As[acol + 0][arow] = av.x;
        As[acol + 1][arow] = av.y;
        As[acol + 2][arow] = av.z;
        As[acol + 3][arow] = av.w;

        *reinterpret_cast<float4*>(&Bg[brow][bcol]) =
            *reinterpret_cast<const float4*>(Wg + (size_t)(k0 + brow) * ID + bn + bcol);
        *reinterpret_cast<float4*>(&Bu[brow][bcol]) =
            *reinterpret_cast<const float4*>(Wu + (size_t)(k0 + brow) * ID + bn + bcol);
        __syncthreads();

#pragma unroll
        for (int k = 0; k < BK; k++) {
            const float4 a0 = *reinterpret_cast<const float4*>(&As[k][ty * 8]);
            const float4 a1 = *reinterpret_cast<const float4*>(&As[k][ty * 8 + 4]);
            ull bg[4], bu[4];
#pragma unroll
            for (int j = 0; j < 4; j++) {
                bg[j] = *reinterpret_cast<const ull*>(&Bg[k][tx * 8 + 2 * j]);
                bu[j] = *reinterpret_cast<const ull*>(&Bu[k][tx * 8 + 2 * j]);
            }
            const float a_[8] = {a0.x, a0.y, a0.z, a0.w, a1.x, a1.y, a1.z, a1.w};
#pragma unroll
            for (int i = 0; i < 8; i++) {
                const ull a2 = pack2(a_[i], a_[i]);
#pragma unroll
                for (int j = 0; j < 4; j++) {
                    accG[i][j] = fma2(a2, bg[j], accG[i][j]);
                    accU[i][j] = fma2(a2, bu[j], accU[i][j]);
                }
            }
        }
        __syncthreads();
    }

    // epilogue: SwiGLU, store hidden
#pragma unroll
    for (int i = 0; i < 8; i++) {
        const int slot = bm + ty * 8 + i;
        if (GATHER && slot >= nrows) continue;
        float* hrow = Hout + (size_t)slot * ID + bn + tx * 8;
#pragma unroll
        for (int j = 0; j < 4; j++) {
            float g0, g1, u0, u1;
            unpack2(accG[i][j], g0, g1);
            unpack2(accU[i][j], u0, u1);
            float2 hv;
            hv.x = u0 / (1.f + expf(-g0));
            hv.y = u1 / (1.f + expf(-g1));
            *reinterpret_cast<float2*>(hrow + 2 * j) = hv;
        }
    }
}

// ---------------------------------------------------------------------------
// Down GEMM.
// SCATTER=false: out[t] = residual[t] + g_hid_s[t] @ Wd            (full write)
// SCATTER=true : atomicAdd(out[tok], w * (g_hid_r[e][slot] @ Wd_e)) (after dense)
// ---------------------------------------------------------------------------
template<bool SCATTER>
__global__ void __launch_bounds__(256, 1)
k_down(const float* __restrict__ Wd_all,
       const float* __restrict__ residual,
       float* __restrict__ out)
{
    constexpr int BM = 128, BN = 128, BK = 8;
    __shared__ float As[BK][BM];
    __shared__ float Bs[BK][BN];

    const int bn = blockIdx.x * BN;
    const int bm = blockIdx.y * BM;

    int nrows;
    const float* Hin;
    const float* Wd;
    const int*   toks = nullptr;
    const float* wts  = nullptr;
    if (SCATTER) {
        const int e = blockIdx.z;
        nrows = g_cnt[e];
        if (bm >= nrows) return;
        Hin  = g_hid_r + (size_t)e * PER_E * ID;
        Wd   = Wd_all + (size_t)e * ID * HD;
        toks = g_tok[e];
        wts  = g_wt[e];
    } else {
        nrows = T_TOK;
        Hin = g_hid_s;
        Wd  = Wd_all;
    }

    const int tid  = threadIdx.x;
    const int arow = tid >> 1,  acol = (tid & 1) * 4;
    const int brow = tid >> 5,  bcol = (tid & 31) * 4;
    const int tx   = tid & 15,  ty   = tid >> 4;

    const int aslot  = bm + arow;
    const bool avalid = (!SCATTER) || (aslot < nrows);

    ull acc[8][4];
#pragma unroll
    for (int i = 0; i < 8; i++)
#pragma unroll
        for (int j = 0; j < 4; j++) acc[i][j] = 0ull;

    for (int k0 = 0; k0 < ID; k0 += BK) {
        float4 av = make_float4(0.f, 0.f, 0.f, 0.f);
        if (avalid)
            av = *reinterpret_cast<const float4*>(Hin + (size_t)aslot * ID + k0 + acol);
        As[acol + 0][arow] = av.x;
        As[acol + 1][arow] = av.y;
        As[acol + 2][arow] = av.z;
        As[acol + 3][arow] = av.w;

        *reinterpret_cast<float4*>(&Bs[brow][bcol]) =
            *reinterpret_cast<const float4*>(Wd + (size_t)(k0 + brow) * HD + bn + bcol);
        __syncthreads();

#pragma unroll
        for (int k = 0; k < BK; k++) {
            const float4 a0 = *reinterpret_cast<const float4*>(&As[k][ty * 8]);
            const float4 a1 = *reinterpret_cast<const float4*>(&As[k][ty * 8 + 4]);
            ull bb[4];
#pragma unroll
            for (int j = 0; j < 4; j++)
                bb[j] = *reinterpret_cast<const ull*>(&Bs[k][tx * 8 + 2 * j]);
            const float a_[8] = {a0.x, a0.y, a0.z, a0.w, a1.x, a1.y, a1.z, a1.w};
#pragma unroll
            for (int i = 0; i < 8; i++) {
                const ull a2 = pack2(a_[i], a_[i]);
#pragma unroll
                for (int j = 0; j < 4; j++)
                    acc[i][j] = fma2(a2, bb[j], acc[i][j]);
            }
        }
        __syncthreads();
    }

#pragma unroll
    for (int i = 0; i < 8; i++) {
        const int slot = bm + ty * 8 + i;
        if (SCATTER) {
            if (slot >= nrows) continue;
            const int   t = toks[slot];
            const float w = wts[slot];
            float* ob = out + (size_t)t * HD + bn + tx * 8;
#pragma unroll
            for (int j = 0; j < 4; j++) {
                float lo, hi;
                unpack2(acc[i][j], lo, hi);
                atomicAdd(ob + 2 * j,     w * lo);
                atomicAdd(ob + 2 * j + 1, w * hi);
            }
        } else {
            const float* rb = residual + (size_t)slot * HD + bn + tx * 8;
            float*       ob = out      + (size_t)slot * HD + bn + tx * 8;
#pragma unroll
            for (int j = 0; j < 4; j++) {
                float lo, hi;
                unpack2(acc[i][j], lo, hi);
                const float2 rv = *reinterpret_cast<const float2*>(rb + 2 * j);
                float2 ov;
                ov.x = rv.x + lo;
                ov.y = rv.y + hi;
                *reinterpret_cast<float2*>(ob + 2 * j) = ov;
            }
        }
    }
}

// ---------------------------------------------------------------------------
// launch
// ---------------------------------------------------------------------------
extern "C" void kernel_launch(void* const* d_in, const int* in_sizes, int n_in,
                              void* d_out, int out_size)
{
    const float* X  = (const float*)d_in[0];   // hidden_states [T, H]
    const float* RW = (const float*)d_in[1];   // router_w [E, H]
    const float* SG = (const float*)d_in[2];   // shared_gate [H, I]
    const float* SU = (const float*)d_in[3];   // shared_up   [H, I]
    const float* SD = (const float*)d_in[4];   // shared_down [I, H]
    const float* EG = (const float*)d_in[5];   // experts_gate [E, H, I]
    const float* EU = (const float*)d_in[6];   // experts_up   [E, H, I]
    const float* ED = (const float*)d_in[7];   // experts_down [E, I, H]
    float* out = (float*)d_out;

    k_init<<<1, 32>>>();
    k_router<<<T_TOK / 4, 128>>>(X, RW);

    // shared expert gate+up (dense)
    k_gateup<false><<<dim3(ID / 128, T_TOK / 128, 1), 256>>>(X, SG, SU);
    // routed experts gate+up (gathered; worst-case grid, early exit)
    k_gateup<true ><<<dim3(ID / 128, PER_E / 128, NE), 256>>>(X, EG, EU);

    // shared down: writes out = residual + shared_out  (full coverage)
    k_down<false><<<dim3(HD / 128, T_TOK / 128, 1), 256>>>(SD, X, out);
    // routed down: atomicAdd of weighted expert outputs
    k_down<true ><<<dim3(HD / 128, PER_E / 128, NE), 256>>>(ED, X, out);
}

// round 4
// speedup vs baseline: 2.4836x; 2.4836x over previous
#include <cuda_runtime.h>
#include <cuda_bf16.h>
#include <math.h>
#include <stdint.h>

// ===========================================================================
// TinyMoE via base-ISA tensor ops (mma.sync bf16, ldmatrix, cp.async).
// 3-term hi/lo bf16 split GEMMs with fp32 accumulation.
// T=4096, H=I=1024, E=8, top-2 routing, route-then-compute.
// ===========================================================================

#define T_TOK 4096
#define HD    1024
#define NE    8
#define RPAD  10240

using bf16 = __nv_bfloat16;

// ---------------- device scratch -------------------------------------------
__device__ bf16  g_xc   [(size_t)T_TOK * 2048];      // X hi|lo
__device__ bf16  g_wsg  [(size_t)1024 * 2048];       // shared gate^T hi|lo [n][k]
__device__ bf16  g_wsu  [(size_t)1024 * 2048];
__device__ bf16  g_wsd  [(size_t)1024 * 2048];
__device__ bf16  g_weg  [(size_t)NE * 1024 * 2048];
__device__ bf16  g_weu  [(size_t)NE * 1024 * 2048];
__device__ bf16  g_wed  [(size_t)NE * 1024 * 2048];
__device__ bf16  g_hid_s[(size_t)T_TOK * 2048];      // shared hidden hi|lo
__device__ bf16  g_hid_r[(size_t)RPAD * 2048];       // routed hidden hi|lo
__device__ float g_scr  [(size_t)RPAD * 1024];       // gate output scratch
__device__ float g_rout [(size_t)RPAD * 1024];       // routed down output
__device__ int   g_cnt[NE];
__device__ int   g_base[NE];
__device__ int   g_tok[NE][T_TOK];
__device__ int   g_sel_e[T_TOK * 2];
__device__ int   g_sel_p[T_TOK * 2];
__device__ float g_sel_w[T_TOK * 2];

// ---------------- asm helpers (base ISA only) ------------------------------
__device__ __forceinline__ uint32_t s2u(const void* p) {
    uint32_t a;
    asm("{ .reg .u64 t; cvta.to.shared.u64 t, %1; cvt.u32.u64 %0, t; }" : "=r"(a) : "l"(p));
    return a;
}
__device__ __forceinline__ void cp16(uint32_t dst, const void* src) {
    asm volatile("cp.async.cg.shared.global [%0], [%1], 16;" :: "r"(dst), "l"(src));
}
__device__ __forceinline__ void cp_commit() {
    asm volatile("cp.async.commit_group;");
}
__device__ __forceinline__ void ldsm4(uint32_t* r, uint32_t addr) {
    asm volatile("ldmatrix.sync.aligned.m8n8.x4.shared.b16 {%0,%1,%2,%3}, [%4];"
        : "=r"(r[0]), "=r"(r[1]), "=r"(r[2]), "=r"(r[3]) : "r"(addr));
}
__device__ __forceinline__ void mma_bf16(float* c, const uint32_t* a, const uint32_t* b) {
    asm volatile(
        "mma.sync.aligned.m16n8k16.row.col.f32.bf16.bf16.f32 "
        "{%0,%1,%2,%3}, {%4,%5,%6,%7}, {%8,%9}, {%0,%1,%2,%3};"
        : "+f"(c[0]), "+f"(c[1]), "+f"(c[2]), "+f"(c[3])
        : "r"(a[0]), "r"(a[1]), "r"(a[2]), "r"(a[3]), "r"(b[0]), "r"(b[1]));
}

// ---------------------------------------------------------------------------
// init / conversions / router
// ---------------------------------------------------------------------------
__global__ void k_init() { if (threadIdx.x < NE) g_cnt[threadIdx.x] = 0; }

__global__ void k_convx(const float* __restrict__ X) {
    const int idx = blockIdx.x * blockDim.x + threadIdx.x;
    const int t = idx >> 8, c = (idx & 255) * 4;
    const float4 v = *reinterpret_cast<const float4*>(X + (size_t)t * 1024 + c);
    bf16 h0 = __float2bfloat16(v.x), h1 = __float2bfloat16(v.y);
    bf16 h2 = __float2bfloat16(v.z), h3 = __float2bfloat16(v.w);
    bf16 l0 = __float2bfloat16(v.x - __bfloat162float(h0));
    bf16 l1 = __float2bfloat16(v.y - __bfloat162float(h1));
    bf16 l2 = __float2bfloat16(v.z - __bfloat162float(h2));
    bf16 l3 = __float2bfloat16(v.w - __bfloat162float(h3));
    bf16* d = g_xc + (size_t)t * 2048 + c;
    d[0] = h0; d[1] = h1; d[2] = h2; d[3] = h3;
    d += 1024;
    d[0] = l0; d[1] = l1; d[2] = l2; d[3] = l3;
}

// transpose-convert W[k,n] fp32 -> Wc[n][2048] hi|lo  (blockIdx.z = matrix)
__global__ void k_convw(const float* __restrict__ src, bf16* __restrict__ dst) {
    __shared__ float t[32][33];
    const float* S = src + (size_t)blockIdx.z * 1024 * 1024;
    bf16* D = dst + (size_t)blockIdx.z * 1024 * 2048;
    const int k0 = blockIdx.y * 32, n0 = blockIdx.x * 32;
    const int tx = threadIdx.x, ty = threadIdx.y;
#pragma unroll
    for (int i = 0; i < 4; i++)
        t[ty + i * 8][tx] = S[(size_t)(k0 + ty + i * 8) * 1024 + n0 + tx];
    __syncthreads();
#pragma unroll
    for (int i = 0; i < 4; i++) {
        const int n = n0 + ty + i * 8;
        const float v = t[tx][ty + i * 8];
        const bf16 h = __float2bfloat16(v);
        const bf16 l = __float2bfloat16(v - __bfloat162float(h));
        D[(size_t)n * 2048 + k0 + tx] = h;
        D[(size_t)n * 2048 + 1024 + k0 + tx] = l;
    }
}

__global__ void k_router(const float* __restrict__ X, const float* __restrict__ RW) {
    const int t = (blockIdx.x * blockDim.x + threadIdx.x) >> 5;
    const int lane = threadIdx.x & 31;
    if (t >= T_TOK) return;
    const float* xr = X + (size_t)t * HD;
    float acc[NE];
#pragma unroll
    for (int e = 0; e < NE; e++) acc[e] = 0.f;
    for (int h = lane; h < HD; h += 32) {
        const float xv = xr[h];
#pragma unroll
        for (int e = 0; e < NE; e++) acc[e] += xv * RW[e * HD + h];
    }
#pragma unroll
    for (int e = 0; e < NE; e++)
#pragma unroll
        for (int off = 16; off > 0; off >>= 1)
            acc[e] += __shfl_down_sync(0xffffffffu, acc[e], off);
    if (lane == 0) {
        float m = acc[0];
#pragma unroll
        for (int e = 1; e < NE; e++) m = fmaxf(m, acc[e]);
        float p[NE], s = 0.f;
#pragma unroll
        for (int e = 0; e < NE; e++) { p[e] = expf(acc[e] - m); s += p[e]; }
        const float inv = 1.f / s;
#pragma unroll
        for (int e = 0; e < NE; e++) p[e] *= inv;
        int i1 = 0; float b1 = p[0];
#pragma unroll
        for (int e = 1; e < NE; e++) if (p[e] > b1) { b1 = p[e]; i1 = e; }
        int i2 = -1; float b2 = -1.f;
#pragma unroll
        for (int e = 0; e < NE; e++) if (e != i1 && p[e] > b2) { b2 = p[e]; i2 = e; }
        int pos = atomicAdd(&g_cnt[i1], 1);
        g_tok[i1][pos] = t;
        g_sel_e[t * 2] = i1; g_sel_p[t * 2] = pos; g_sel_w[t * 2] = b1;
        pos = atomicAdd(&g_cnt[i2], 1);
        g_tok[i2][pos] = t;
        g_sel_e[t * 2 + 1] = i2; g_sel_p[t * 2 + 1] = pos; g_sel_w[t * 2 + 1] = b2;
    }
}

__global__ void k_offsets() {
    if (threadIdx.x == 0) {
        int b = 0;
        for (int e = 0; e < NE; e++) { g_base[e] = b; b += (g_cnt[e] + 127) & ~127; }
    }
}

// ---------------------------------------------------------------------------
// GEMM: C[128x128] = A(hi+lo) @ B(hi+lo)^T, 3-term bf16 mma.sync.
// A: [rows][2048] hi|lo row-major; B: [1024][2048] hi|lo (K-major, "B^T").
// smem tile layout: 128 rows x 128B (chunks 0-3 = hi K0..31, 4-7 = lo),
// swizzle: chunk ^= row&7  -> conflict-free cp.async stores + ldmatrix reads.
// EPI: 0=store fp32 scr, 1=SwiGLU (read scr as gate, write hidden hi/lo),
//      2=out = X + C (dense down), 3=store to g_rout (routed down).
// ---------------------------------------------------------------------------
#define SMEMSZ 65536

template<int EXPERT, int GATHER, int EPI>
__global__ void __launch_bounds__(256)
k_gemm(const bf16* __restrict__ A, const bf16* __restrict__ B,
       const float* __restrict__ aux, float* __restrict__ outf,
       bf16* __restrict__ outh)
{
    extern __shared__ char smraw[];
    const uint32_t smu = s2u(smraw);
    const int tid = threadIdx.x;
    const int bn = blockIdx.x * 128;
    const int bm = blockIdx.y * 128;

    int rbase = 0, cnt = 0;
    const int* toks = nullptr;
    if (EXPERT) {
        const int e = blockIdx.z;
        cnt = g_cnt[e];
        if (bm >= cnt) return;
        rbase = g_base[e];
        B += (size_t)e * 1024 * 2048;
        if (GATHER) toks = g_tok[e];
    }

    // ---- per-thread load mapping: 8 x 16B cp.async per stage ----
    const int lr = tid >> 3;          // row within 32-row group
    const int lc = tid & 7;           // 16B chunk 0..7
    const int coff = (lc < 4) ? lc * 8 : 1024 + (lc - 4) * 8;   // bf16 elems

    const bf16* arp[4];
    const bf16* brp[4];
#pragma unroll
    for (int i = 0; i < 4; i++) {
        const int slot = bm + lr + 32 * i;
        int arow;
        if (GATHER) {
            int s = slot < cnt - 1 ? slot : cnt - 1;
            arow = toks[s];
        } else {
            arow = (EXPERT ? rbase : 0) + slot;
        }
        arp[i] = A + (size_t)arow * 2048 + coff;
        brp[i] = B + (size_t)(bn + lr + 32 * i) * 2048 + coff;
    }
    // dst offsets (swizzled) are k-invariant
    uint32_t dA[4], dB[4];
#pragma unroll
    for (int i = 0; i < 4; i++) {
        const int r = lr + 32 * i;
        const uint32_t o = (uint32_t)(r * 128 + ((lc ^ (r & 7)) << 4));
        dA[i] = o; dB[i] = 16384u + o;
    }

    const int lane = tid & 31, w = tid >> 5;
    const int m0 = (w & 3) * 32, n0 = (w >> 2) * 64;

    float acc[2][8][4];
#pragma unroll
    for (int mf = 0; mf < 2; mf++)
#pragma unroll
        for (int nf = 0; nf < 8; nf++)
#pragma unroll
            for (int j = 0; j < 4; j++) acc[mf][nf][j] = 0.f;

    // ---- prefetch stage 0 ----
    {
        const uint32_t sa = smu;
#pragma unroll
        for (int i = 0; i < 4; i++) { cp16(sa + dA[i], arp[i]); cp16(sa + dB[i], brp[i]); }
        cp_commit();
    }

    // precompute ldmatrix addresses (stage-relative, k16-step varying part added in loop)
    const int ar_ = (lane & 15);
    const int ac_ = (lane >> 4);
    const int br_ = (lane & 7) + ((lane >> 4) << 3);
    const int bc_ = ((lane >> 3) & 1);

    for (int it = 0; it < 32; ++it) {
        if (it + 1 < 32) {
            const int kb = (it + 1) * 32;
            const uint32_t sa = smu + ((it + 1) & 1) * 32768u;
#pragma unroll
            for (int i = 0; i < 4; i++) {
                cp16(sa + dA[i], arp[i] + kb);
                cp16(sa + dB[i], brp[i] + kb);
            }
            cp_commit();
            asm volatile("cp.async.wait_group 1;");
        } else {
            asm volatile("cp.async.wait_group 0;");
        }
        __syncthreads();

        const uint32_t sa = smu + (it & 1) * 32768u;
        const uint32_t sb = sa + 16384u;
#pragma unroll
        for (int s = 0; s < 2; s++) {
            uint32_t ah[2][4], al[2][4], bh[4][4], bl[4][4];
#pragma unroll
            for (int mf = 0; mf < 2; mf++) {
                const int r = m0 + mf * 16 + ar_;
                const int c = s * 2 + ac_;
                ldsm4(ah[mf], sa + r * 128 + (((c)     ^ (r & 7)) << 4));
                ldsm4(al[mf], sa + r * 128 + (((c + 4) ^ (r & 7)) << 4));
            }
#pragma unroll
            for (int bi = 0; bi < 4; bi++) {
                const int nr = n0 + bi * 16 + br_;
                const int c = s * 2 + bc_;
                ldsm4(bh[bi], sb + nr * 128 + (((c)     ^ (nr & 7)) << 4));
                ldsm4(bl[bi], sb + nr * 128 + (((c + 4) ^ (nr & 7)) << 4));
            }
#pragma unroll
            for (int mf = 0; mf < 2; mf++)
#pragma unroll
                for (int nf = 0; nf < 8; nf++) {
                    const uint32_t* bph = &bh[nf >> 1][(nf & 1) * 2];
                    const uint32_t* bpl = &bl[nf >> 1][(nf & 1) * 2];
                    mma_bf16(acc[mf][nf], ah[mf], bph);
                    mma_bf16(acc[mf][nf], al[mf], bph);
                    mma_bf16(acc[mf][nf], ah[mf], bpl);
                }
        }
        __syncthreads();
    }

    // ---- epilogue ----
    const int mr = lane >> 2, nc2 = (lane & 3) * 2;
#pragma unroll
    for (int mf = 0; mf < 2; mf++)
#pragma unroll
        for (int nf = 0; nf < 8; nf++)
#pragma unroll
            for (int h = 0; h < 2; h++) {
                const int rl = m0 + mf * 16 + mr + h * 8;
                const int col = bn + n0 + nf * 8 + nc2;
                const float c0 = acc[mf][nf][h * 2], c1 = acc[mf][nf][h * 2 + 1];
                const int orow = rbase + bm + rl;
                if (EPI == 0) {
                    float2 v = make_float2(c0, c1);
                    *reinterpret_cast<float2*>(outf + (size_t)orow * 1024 + col) = v;
                } else if (EPI == 1) {
                    const float2 g = *reinterpret_cast<const float2*>(aux + (size_t)orow * 1024 + col);
                    const float v0 = c0 / (1.f + expf(-g.x));
                    const float v1 = c1 / (1.f + expf(-g.y));
                    bf16 h0 = __float2bfloat16(v0), h1 = __float2bfloat16(v1);
                    bf16 l0 = __float2bfloat16(v0 - __bfloat162float(h0));
                    bf16 l1 = __float2bfloat16(v1 - __bfloat162float(h1));
                    uint32_t hp, lp;
                    {
                        uint16_t a0 = *(uint16_t*)&h0, a1 = *(uint16_t*)&h1;
                        uint16_t b0 = *(uint16_t*)&l0, b1 = *(uint16_t*)&l1;
                        hp = (uint32_t)a0 | ((uint32_t)a1 << 16);
                        lp = (uint32_t)b0 | ((uint32_t)b1 << 16);
                    }
                    *reinterpret_cast<uint32_t*>(outh + (size_t)orow * 2048 + col) = hp;
                    *reinterpret_cast<uint32_t*>(outh + (size_t)orow * 2048 + 1024 + col) = lp;
                } else if (EPI == 2) {
                    const int t = bm + rl;
                    const float2 rv = *reinterpret_cast<const float2*>(aux + (size_t)t * 1024 + col);
                    float2 v = make_float2(rv.x + c0, rv.y + c1);
                    *reinterpret_cast<float2*>(outf + (size_t)t * 1024 + col) = v;
                } else {
                    float2 v = make_float2(c0, c1);
                    *reinterpret_cast<float2*>(outf + (size_t)orow * 1024 + col) = v;
                }
            }
}

// ---------------------------------------------------------------------------
// combine: out[t] += w1*rout[slot1] + w2*rout[slot2]
// ---------------------------------------------------------------------------
__global__ void k_combine(float* __restrict__ out) {
    const int t = blockIdx.x;
    const int e1 = g_sel_e[t * 2],     p1 = g_sel_p[t * 2];
    const int e2 = g_sel_e[t * 2 + 1], p2 = g_sel_p[t * 2 + 1];
    const float w1 = g_sel_w[t * 2], w2 = g_sel_w[t * 2 + 1];
    const float* r1 = g_rout + (size_t)(g_base[e1] + p1) * 1024;
    const float* r2 = g_rout + (size_t)(g_base[e2] + p2) * 1024;
    float* o = out + (size_t)t * 1024;
#pragma unroll
    for (int k = 0; k < 2; k++) {
        const int j = (threadIdx.x + k * 128) * 4;
        const float4 a = *(const float4*)(r1 + j);
        const float4 b = *(const float4*)(r2 + j);
        float4 v = *(float4*)(o + j);
        v.x += w1 * a.x + w2 * b.x; v.y += w1 * a.y + w2 * b.y;
        v.z += w1 * a.z + w2 * b.z; v.w += w1 * a.w + w2 * b.w;
        *(float4*)(o + j) = v;
    }
}

// ---------------------------------------------------------------------------
// launch
// ---------------------------------------------------------------------------
extern "C" void kernel_launch(void* const* d_in, const int* in_sizes, int n_in,
                              void* d_out, int out_size)
{
    const float* X  = (const float*)d_in[0];
    const float* RW = (const float*)d_in[1];
    const float* SG = (const float*)d_in[2];
    const float* SU = (const float*)d_in[3];
    const float* SD = (const float*)d_in[4];
    const float* EG = (const float*)d_in[5];
    const float* EU = (const float*)d_in[6];
    const float* ED = (const float*)d_in[7];
    float* out = (float*)d_out;

    static bool once = false;
    if (!once) {
        cudaFuncSetAttribute(k_gemm<0,0,0>, cudaFuncAttributeMaxDynamicSharedMemorySize, SMEMSZ);
        cudaFuncSetAttribute(k_gemm<0,0,1>, cudaFuncAttributeMaxDynamicSharedMemorySize, SMEMSZ);
        cudaFuncSetAttribute(k_gemm<1,1,0>, cudaFuncAttributeMaxDynamicSharedMemorySize, SMEMSZ);
        cudaFuncSetAttribute(k_gemm<1,1,1>, cudaFuncAttributeMaxDynamicSharedMemorySize, SMEMSZ);
        cudaFuncSetAttribute(k_gemm<0,0,2>, cudaFuncAttributeMaxDynamicSharedMemorySize, SMEMSZ);
        cudaFuncSetAttribute(k_gemm<1,0,3>, cudaFuncAttributeMaxDynamicSharedMemorySize, SMEMSZ);
        once = true;
    }

    bf16 *xc, *wsg, *wsu, *wsd, *weg, *weu, *wed, *hids, *hidr;
    float *scr, *rout;
    cudaGetSymbolAddress((void**)&xc,   g_xc);
    cudaGetSymbolAddress((void**)&wsg,  g_wsg);
    cudaGetSymbolAddress((void**)&wsu,  g_wsu);
    cudaGetSymbolAddress((void**)&wsd,  g_wsd);
    cudaGetSymbolAddress((void**)&weg,  g_weg);
    cudaGetSymbolAddress((void**)&weu,  g_weu);
    cudaGetSymbolAddress((void**)&wed,  g_wed);
    cudaGetSymbolAddress((void**)&hids, g_hid_s);
    cudaGetSymbolAddress((void**)&hidr, g_hid_r);
    cudaGetSymbolAddress((void**)&scr,  g_scr);
    cudaGetSymbolAddress((void**)&rout, g_rout);

    k_init<<<1, 32>>>();
    k_convx<<<4096, 256>>>(X);
    dim3 cb(32, 8);
    k_convw<<<dim3(32, 32, 1),  cb>>>(SG, wsg);
    k_convw<<<dim3(32, 32, 1),  cb>>>(SU, wsu);
    k_convw<<<dim3(32, 32, 1),  cb>>>(SD, wsd);
    k_convw<<<dim3(32, 32, NE), cb>>>(EG, weg);
    k_convw<<<dim3(32, 32, NE), cb>>>(EU, weu);
    k_convw<<<dim3(32, 32, NE), cb>>>(ED, wed);

    k_router<<<1024, 128>>>(X, RW);
    k_offsets<<<1, 32>>>();

    // shared expert: gate -> scr, up (+SwiGLU) -> hid_s
    k_gemm<0,0,0><<<dim3(8, 32), 256, SMEMSZ>>>(xc, wsg, nullptr, scr, nullptr);
    k_gemm<0,0,1><<<dim3(8, 32), 256, SMEMSZ>>>(xc, wsu, scr, nullptr, hids);
    // routed experts: gathered gate -> scr (compact), up (+SwiGLU) -> hid_r
    k_gemm<1,1,0><<<dim3(8, 32, NE), 256, SMEMSZ>>>(xc, weg, nullptr, scr, nullptr);
    k_gemm<1,1,1><<<dim3(8, 32, NE), 256, SMEMSZ>>>(xc, weu, scr, nullptr, hidr);
    // down: dense writes out = X + C; routed writes rout
    k_gemm<0,0,2><<<dim3(8, 32), 256, SMEMSZ>>>(hids, wsd, X, out, nullptr);
    k_gemm<1,0,3><<<dim3(8, 32, NE), 256, SMEMSZ>>>(hidr, wed, nullptr, rout, nullptr);

    k_combine<<<T_TOK, 128>>>(out);
}

// round 5
// speedup vs baseline: 2.8699x; 1.1556x over previous
#include <cuda_runtime.h>
#include <cuda_bf16.h>
#include <math.h>
#include <stdint.h>

// ===========================================================================
// TinyMoE via base-ISA tensor ops (mma.sync bf16, ldmatrix, cp.async).
// 3-term hi/lo bf16 split GEMMs, fp32 accumulation.
// R5: fused gate+up (512 thr), packed conversions, 3-stage pipelines.
// ===========================================================================

#define T_TOK 4096
#define HD    1024
#define NE    8
#define RPAD  10240

using bf16 = __nv_bfloat16;

// ---------------- device scratch -------------------------------------------
__device__ bf16  g_xc   [(size_t)T_TOK * 2048];      // X hi|lo
__device__ bf16  g_wsg  [(size_t)1024 * 2048];       // shared gate^T hi|lo [n][k]
__device__ bf16  g_wsu  [(size_t)1024 * 2048];
__device__ bf16  g_wsd  [(size_t)1024 * 2048];
__device__ bf16  g_weg  [(size_t)NE * 1024 * 2048];
__device__ bf16  g_weu  [(size_t)NE * 1024 * 2048];
__device__ bf16  g_wed  [(size_t)NE * 1024 * 2048];
__device__ bf16  g_hid_s[(size_t)T_TOK * 2048];      // shared hidden hi|lo
__device__ bf16  g_hid_r[(size_t)RPAD * 2048];       // routed hidden hi|lo
__device__ float g_rout [(size_t)RPAD * 1024];       // routed down output
__device__ int   g_cnt[NE];
__device__ int   g_base[NE];
__device__ int   g_tok[NE][T_TOK];
__device__ int   g_sel_e[T_TOK * 2];
__device__ int   g_sel_p[T_TOK * 2];
__device__ float g_sel_w[T_TOK * 2];

// ---------------- asm helpers (base ISA only) ------------------------------
__device__ __forceinline__ uint32_t s2u(const void* p) {
    uint32_t a;
    asm("{ .reg .u64 t; cvta.to.shared.u64 t, %1; cvt.u32.u64 %0, t; }" : "=r"(a) : "l"(p));
    return a;
}
__device__ __forceinline__ void cp16(uint32_t dst, const void* src) {
    asm volatile("cp.async.cg.shared.global [%0], [%1], 16;" :: "r"(dst), "l"(src));
}
__device__ __forceinline__ void cp_commit() {
    asm volatile("cp.async.commit_group;");
}
__device__ __forceinline__ void cp_wait2() {
    asm volatile("cp.async.wait_group 2;");
}
__device__ __forceinline__ void ldsm4(uint32_t* r, uint32_t addr) {
    asm volatile("ldmatrix.sync.aligned.m8n8.x4.shared.b16 {%0,%1,%2,%3}, [%4];"
        : "=r"(r[0]), "=r"(r[1]), "=r"(r[2]), "=r"(r[3]) : "r"(addr));
}
__device__ __forceinline__ void mma_bf16(float* c, const uint32_t* a, const uint32_t* b) {
    asm volatile(
        "mma.sync.aligned.m16n8k16.row.col.f32.bf16.bf16.f32 "
        "{%0,%1,%2,%3}, {%4,%5,%6,%7}, {%8,%9}, {%0,%1,%2,%3};"
        : "+f"(c[0]), "+f"(c[1]), "+f"(c[2]), "+f"(c[3])
        : "r"(a[0]), "r"(a[1]), "r"(a[2]), "r"(a[3]), "r"(b[0]), "r"(b[1]));
}
// pack two floats -> (hi bf16 pair, lo bf16 pair)
__device__ __forceinline__ void hilo2(float a, float b, uint32_t& hp, uint32_t& lp) {
    bf16 h0 = __float2bfloat16(a), h1 = __float2bfloat16(b);
    bf16 l0 = __float2bfloat16(a - __bfloat162float(h0));
    bf16 l1 = __float2bfloat16(b - __bfloat162float(h1));
    hp = (uint32_t)*(uint16_t*)&h0 | ((uint32_t)*(uint16_t*)&h1 << 16);
    lp = (uint32_t)*(uint16_t*)&l0 | ((uint32_t)*(uint16_t*)&l1 << 16);
}

// ---------------------------------------------------------------------------
// init / conversions / router
// ---------------------------------------------------------------------------
__global__ void k_init() { if (threadIdx.x < NE) g_cnt[threadIdx.x] = 0; }

// X fp32 [t][1024] -> g_xc [t][2048] hi|lo, 16B stores
__global__ void k_convx(const float* __restrict__ X) {
    const int idx = blockIdx.x * blockDim.x + threadIdx.x;   // 524288
    const int t = idx >> 7, c = (idx & 127) * 8;
    const float4 v0 = *reinterpret_cast<const float4*>(X + (size_t)t * 1024 + c);
    const float4 v1 = *reinterpret_cast<const float4*>(X + (size_t)t * 1024 + c + 4);
    uint4 hv, lv;
    hilo2(v0.x, v0.y, hv.x, lv.x);
    hilo2(v0.z, v0.w, hv.y, lv.y);
    hilo2(v1.x, v1.y, hv.z, lv.z);
    hilo2(v1.z, v1.w, hv.w, lv.w);
    *reinterpret_cast<uint4*>(g_xc + (size_t)t * 2048 + c) = hv;
    *reinterpret_cast<uint4*>(g_xc + (size_t)t * 2048 + 1024 + c) = lv;
}

// transpose-convert W[k][n] fp32 -> Wc[n][2048] hi|lo, 8B stores
__global__ void __launch_bounds__(256) k_convw(const float* __restrict__ src, bf16* __restrict__ dst) {
    __shared__ float t[32][33];
    src += (size_t)blockIdx.z * 1024 * 1024;
    dst += (size_t)blockIdx.z * 1024 * 2048;
    const int k0 = blockIdx.y * 32, n0 = blockIdx.x * 32;
    const int tid = threadIdx.x;
#pragma unroll
    for (int i = 0; i < 4; i++) {
        const int e = tid + i * 256;
        const int kk = e >> 5, nn = e & 31;
        t[kk][nn] = src[(size_t)(k0 + kk) * 1024 + n0 + nn];
    }
    __syncthreads();
    const int nl = tid >> 3, kq = (tid & 7) * 4;
    const float a0 = t[kq][nl], a1 = t[kq + 1][nl], a2 = t[kq + 2][nl], a3 = t[kq + 3][nl];
    uint2 hv, lv;
    hilo2(a0, a1, hv.x, lv.x);
    hilo2(a2, a3, hv.y, lv.y);
    bf16* drow = dst + (size_t)(n0 + nl) * 2048 + k0 + kq;
    *reinterpret_cast<uint2*>(drow) = hv;
    *reinterpret_cast<uint2*>(drow + 1024) = lv;
}

__global__ void k_router(const float* __restrict__ X, const float* __restrict__ RW) {
    const int t = (blockIdx.x * blockDim.x + threadIdx.x) >> 5;
    const int lane = threadIdx.x & 31;
    if (t >= T_TOK) return;
    const float* xr = X + (size_t)t * HD;
    float acc[NE];
#pragma unroll
    for (int e = 0; e < NE; e++) acc[e] = 0.f;
    for (int h = lane; h < HD; h += 32) {
        const float xv = xr[h];
#pragma unroll
        for (int e = 0; e < NE; e++) acc[e] += xv * RW[e * HD + h];
    }
#pragma unroll
    for (int e = 0; e < NE; e++)
#pragma unroll
        for (int off = 16; off > 0; off >>= 1)
            acc[e] += __shfl_down_sync(0xffffffffu, acc[e], off);
    if (lane == 0) {
        float m = acc[0];
#pragma unroll
        for (int e = 1; e < NE; e++) m = fmaxf(m, acc[e]);
        float p[NE], s = 0.f;
#pragma unroll
        for (int e = 0; e < NE; e++) { p[e] = expf(acc[e] - m); s += p[e]; }
        const float inv = 1.f / s;
#pragma unroll
        for (int e = 0; e < NE; e++) p[e] *= inv;
        int i1 = 0; float b1 = p[0];
#pragma unroll
        for (int e = 1; e < NE; e++) if (p[e] > b1) { b1 = p[e]; i1 = e; }
        int i2 = -1; float b2 = -1.f;
#pragma unroll
        for (int e = 0; e < NE; e++) if (e != i1 && p[e] > b2) { b2 = p[e]; i2 = e; }
        int pos = atomicAdd(&g_cnt[i1], 1);
        g_tok[i1][pos] = t;
        g_sel_e[t * 2] = i1; g_sel_p[t * 2] = pos; g_sel_w[t * 2] = b1;
        pos = atomicAdd(&g_cnt[i2], 1);
        g_tok[i2][pos] = t;
        g_sel_e[t * 2 + 1] = i2; g_sel_p[t * 2 + 1] = pos; g_sel_w[t * 2 + 1] = b2;
    }
}

__global__ void k_offsets() {
    if (threadIdx.x == 0) {
        int b = 0;
        for (int e = 0; e < NE; e++) { g_base[e] = b; b += (g_cnt[e] + 127) & ~127; }
    }
}

// ---------------------------------------------------------------------------
// Fused gate+up GEMM + SwiGLU.  C_g, C_u [128x128] tiles, 512 threads,
// warp tile 32x32 per matrix, A tile shared. 3-stage cp.async pipeline.
// Writes hidden hi|lo bf16 directly (dense -> g_hid_s, gather -> g_hid_r).
// smem stage = A(16K) + Bg(16K) + Bu(16K) = 48KB, x3 stages.
// ---------------------------------------------------------------------------
#define GU_STG   49152
#define GU_SMEM  (3 * GU_STG)

template<int GATHER>
__global__ void __launch_bounds__(512)
k_gateup(const bf16* __restrict__ A, const bf16* __restrict__ Bg_all,
         const bf16* __restrict__ Bu_all, bf16* __restrict__ Hout)
{
    extern __shared__ char smraw[];
    const uint32_t smu = s2u(smraw);
    const int tid = threadIdx.x;
    const int bn = blockIdx.x * 128;
    const int bm = blockIdx.y * 128;

    const bf16 *Bg = Bg_all, *Bu = Bu_all;
    const int* toks = nullptr;
    int cnt = 0;
    if (GATHER) {
        const int e = blockIdx.z;
        cnt = g_cnt[e];
        if (bm >= cnt) return;
        toks = g_tok[e];
        Bg += (size_t)e * 1024 * 2048;
        Bu += (size_t)e * 1024 * 2048;
        Hout += (size_t)g_base[e] * 2048;
    }

    // ---- load mapping: per thread 2 A chunks + 2 Bg + 2 Bu (16B each) ----
    const int lr = tid >> 3;               // 0..63
    const int lc = tid & 7;
    const int coff = (lc < 4) ? lc * 8 : 1024 + (lc - 4) * 8;

    const bf16 *arp[2], *bgp[2], *bup[2];
    uint32_t dA[2], dBg[2], dBu[2];
#pragma unroll
    for (int i = 0; i < 2; i++) {
        const int r = lr + 64 * i;
        int arow;
        if (GATHER) {
            const int slot = bm + r;
            arow = toks[slot < cnt - 1 ? slot : cnt - 1];
        } else {
            arow = bm + r;
        }
        arp[i] = A + (size_t)arow * 2048 + coff;
        bgp[i] = Bg + (size_t)(bn + r) * 2048 + coff;
        bup[i] = Bu + (size_t)(bn + r) * 2048 + coff;
        const uint32_t o = (uint32_t)(r * 128 + ((lc ^ (r & 7)) << 4));
        dA[i] = o; dBg[i] = 16384u + o; dBu[i] = 32768u + o;
    }

    const int lane = tid & 31, w = tid >> 5;
    const int m0 = (w & 3) * 32, n0 = (w >> 2) * 32;

    float accG[2][4][4], accU[2][4][4];
#pragma unroll
    for (int mf = 0; mf < 2; mf++)
#pragma unroll
        for (int nf = 0; nf < 4; nf++)
#pragma unroll
            for (int j = 0; j < 4; j++) { accG[mf][nf][j] = 0.f; accU[mf][nf][j] = 0.f; }

    // prefetch stages 0,1
#pragma unroll
    for (int st = 0; st < 2; st++) {
        const uint32_t sa = smu + st * GU_STG;
        const int kb = st * 32;
#pragma unroll
        for (int i = 0; i < 2; i++) {
            cp16(sa + dA[i],  arp[i] + kb);
            cp16(sa + dBg[i], bgp[i] + kb);
            cp16(sa + dBu[i], bup[i] + kb);
        }
        cp_commit();
    }

    const int ar_ = lane & 15;
    const int ac_ = lane >> 4;
    const int br_ = (lane & 7) + ((lane >> 4) << 3);
    const int bc_ = (lane >> 3) & 1;

    int stw = 2;   // next stage slot to fill (mod 3)
    for (int it = 0; it < 32; ++it) {
        if (it + 2 < 32) {
            const uint32_t sa = smu + stw * GU_STG;
            const int kb = (it + 2) * 32;
#pragma unroll
            for (int i = 0; i < 2; i++) {
                cp16(sa + dA[i],  arp[i] + kb);
                cp16(sa + dBg[i], bgp[i] + kb);
                cp16(sa + dBu[i], bup[i] + kb);
            }
            stw = (stw + 1) == 3 ? 0 : stw + 1;
        }
        cp_commit();
        cp_wait2();
        __syncthreads();

        const uint32_t sa = smu + (it % 3) * GU_STG;
        const uint32_t sg = sa + 16384u, su = sa + 32768u;
#pragma unroll
        for (int s = 0; s < 2; s++) {
            uint32_t ah[2][4], al[2][4];
#pragma unroll
            for (int mf = 0; mf < 2; mf++) {
                const int r = m0 + mf * 16 + ar_;
                const int c = s * 2 + ac_;
                ldsm4(ah[mf], sa + r * 128 + (((c)     ^ (r & 7)) << 4));
                ldsm4(al[mf], sa + r * 128 + (((c + 4) ^ (r & 7)) << 4));
            }
            {
                uint32_t bh[2][4], bl[2][4];
#pragma unroll
                for (int bi = 0; bi < 2; bi++) {
                    const int nr = n0 + bi * 16 + br_;
                    const int c = s * 2 + bc_;
                    ldsm4(bh[bi], sg + nr * 128 + (((c)     ^ (nr & 7)) << 4));
                    ldsm4(bl[bi], sg + nr * 128 + (((c + 4) ^ (nr & 7)) << 4));
                }
#pragma unroll
                for (int mf = 0; mf < 2; mf++)
#pragma unroll
                    for (int nf = 0; nf < 4; nf++) {
                        const uint32_t* ph = &bh[nf >> 1][(nf & 1) * 2];
                        const uint32_t* pl = &bl[nf >> 1][(nf & 1) * 2];
                        mma_bf16(accG[mf][nf], ah[mf], ph);
                        mma_bf16(accG[mf][nf], al[mf], ph);
                        mma_bf16(accG[mf][nf], ah[mf], pl);
                    }
            }
            {
                uint32_t bh[2][4], bl[2][4];
#pragma unroll
                for (int bi = 0; bi < 2; bi++) {
                    const int nr = n0 + bi * 16 + br_;
                    const int c = s * 2 + bc_;
                    ldsm4(bh[bi], su + nr * 128 + (((c)     ^ (nr & 7)) << 4));
                    ldsm4(bl[bi], su + nr * 128 + (((c + 4) ^ (nr & 7)) << 4));
                }
#pragma unroll
                for (int mf = 0; mf < 2; mf++)
#pragma unroll
                    for (int nf = 0; nf < 4; nf++) {
                        const uint32_t* ph = &bh[nf >> 1][(nf & 1) * 2];
                        const uint32_t* pl = &bl[nf >> 1][(nf & 1) * 2];
                        mma_bf16(accU[mf][nf], ah[mf], ph);
                        mma_bf16(accU[mf][nf], al[mf], ph);
                        mma_bf16(accU[mf][nf], ah[mf], pl);
                    }
            }
        }
        __syncthreads();
    }

    // ---- SwiGLU epilogue: hidden = sigmoid(G)*U, write hi/lo bf16 ----
    const int mr = lane >> 2, nc2 = (lane & 3) * 2;
#pragma unroll
    for (int mf = 0; mf < 2; mf++)
#pragma unroll
        for (int nf = 0; nf < 4; nf++)
#pragma unroll
            for (int h = 0; h < 2; h++) {
                const int rl = m0 + mf * 16 + mr + h * 8;
                const int col = bn + n0 + nf * 8 + nc2;
                const float g0 = accG[mf][nf][h * 2], g1 = accG[mf][nf][h * 2 + 1];
                const float u0 = accU[mf][nf][h * 2], u1 = accU[mf][nf][h * 2 + 1];
                const float v0 = u0 / (1.f + expf(-g0));
                const float v1 = u1 / (1.f + expf(-g1));
                uint32_t hp, lp;
                hilo2(v0, v1, hp, lp);
                bf16* hrow = Hout + (size_t)(bm + rl) * 2048 + col;
                *reinterpret_cast<uint32_t*>(hrow) = hp;
                *reinterpret_cast<uint32_t*>(hrow + 1024) = lp;
            }
}

// ---------------------------------------------------------------------------
// Down GEMM (256 threads, warp tile 32x64, 3-stage pipeline).
// EPI 0: out = X + C (dense).  EPI 1: g_rout = C (routed, compact rows).
// ---------------------------------------------------------------------------
#define DN_STG   32768
#define DN_SMEM  (3 * DN_STG)

template<int EXPERT, int EPI>
__global__ void __launch_bounds__(256)
k_down(const bf16* __restrict__ A, const bf16* __restrict__ B_all,
       const float* __restrict__ aux, float* __restrict__ outf)
{
    extern __shared__ char smraw[];
    const uint32_t smu = s2u(smraw);
    const int tid = threadIdx.x;
    const int bn = blockIdx.x * 128;
    const int bm = blockIdx.y * 128;

    const bf16* B = B_all;
    int rbase = 0;
    if (EXPERT) {
        const int e = blockIdx.z;
        const int cnt = g_cnt[e];
        if (bm >= cnt) return;
        rbase = g_base[e];
        B += (size_t)e * 1024 * 2048;
    }

    const int lr = tid >> 3;
    const int lc = tid & 7;
    const int coff = (lc < 4) ? lc * 8 : 1024 + (lc - 4) * 8;

    const bf16 *arp[4], *brp[4];
    uint32_t dA[4], dB[4];
#pragma unroll
    for (int i = 0; i < 4; i++) {
        const int r = lr + 32 * i;
        arp[i] = A + (size_t)(rbase + bm + r) * 2048 + coff;
        brp[i] = B + (size_t)(bn + r) * 2048 + coff;
        const uint32_t o = (uint32_t)(r * 128 + ((lc ^ (r & 7)) << 4));
        dA[i] = o; dB[i] = 16384u + o;
    }

    const int lane = tid & 31, w = tid >> 5;
    const int m0 = (w & 3) * 32, n0 = (w >> 2) * 64;

    float acc[2][8][4];
#pragma unroll
    for (int mf = 0; mf < 2; mf++)
#pragma unroll
        for (int nf = 0; nf < 8; nf++)
#pragma unroll
            for (int j = 0; j < 4; j++) acc[mf][nf][j] = 0.f;

#pragma unroll
    for (int st = 0; st < 2; st++) {
        const uint32_t sa = smu + st * DN_STG;
        const int kb = st * 32;
#pragma unroll
        for (int i = 0; i < 4; i++) { cp16(sa + dA[i], arp[i] + kb); cp16(sa + dB[i], brp[i] + kb); }
        cp_commit();
    }

    const int ar_ = lane & 15;
    const int ac_ = lane >> 4;
    const int br_ = (lane & 7) + ((lane >> 4) << 3);
    const int bc_ = (lane >> 3) & 1;

    int stw = 2;
    for (int it = 0; it < 32; ++it) {
        if (it + 2 < 32) {
            const uint32_t sa = smu + stw * DN_STG;
            const int kb = (it + 2) * 32;
#pragma unroll
            for (int i = 0; i < 4; i++) { cp16(sa + dA[i], arp[i] + kb); cp16(sa + dB[i], brp[i] + kb); }
            stw = (stw + 1) == 3 ? 0 : stw + 1;
        }
        cp_commit();
        cp_wait2();
        __syncthreads();

        const uint32_t sa = smu + (it % 3) * DN_STG;
        const uint32_t sb = sa + 16384u;
#pragma unroll
        for (int s = 0; s < 2; s++) {
            uint32_t ah[2][4], al[2][4], bh[4][4], bl[4][4];
#pragma unroll
            for (int mf = 0; mf < 2; mf++) {
                const int r = m0 + mf * 16 + ar_;
                const int c = s * 2 + ac_;
                ldsm4(ah[mf], sa + r * 128 + (((c)     ^ (r & 7)) << 4));
                ldsm4(al[mf], sa + r * 128 + (((c + 4) ^ (r & 7)) << 4));
            }
#pragma unroll
            for (int bi = 0; bi < 4; bi++) {
                const int nr = n0 + bi * 16 + br_;
                const int c = s * 2 + bc_;
                ldsm4(bh[bi], sb + nr * 128 + (((c)     ^ (nr & 7)) << 4));
                ldsm4(bl[bi], sb + nr * 128 + (((c + 4) ^ (nr & 7)) << 4));
            }
#pragma unroll
            for (int mf = 0; mf < 2; mf++)
#pragma unroll
                for (int nf = 0; nf < 8; nf++) {
                    const uint32_t* ph = &bh[nf >> 1][(nf & 1) * 2];
                    const uint32_t* pl = &bl[nf >> 1][(nf & 1) * 2];
                    mma_bf16(acc[mf][nf], ah[mf], ph);
                    mma_bf16(acc[mf][nf], al[mf], ph);
                    mma_bf16(acc[mf][nf], ah[mf], pl);
                }
        }
        __syncthreads();
    }

    const int mr = lane >> 2, nc2 = (lane & 3) * 2;
#pragma unroll
    for (int mf = 0; mf < 2; mf++)
#pragma unroll
        for (int nf = 0; nf < 8; nf++)
#pragma unroll
            for (int h = 0; h < 2; h++) {
                const int rl = m0 + mf * 16 + mr + h * 8;
                const int col = bn + n0 + nf * 8 + nc2;
                const float c0 = acc[mf][nf][h * 2], c1 = acc[mf][nf][h * 2 + 1];
                if (EPI == 0) {
                    const int t = bm + rl;
                    const float2 rv = *reinterpret_cast<const float2*>(aux + (size_t)t * 1024 + col);
                    float2 v = make_float2(rv.x + c0, rv.y + c1);
                    *reinterpret_cast<float2*>(outf + (size_t)t * 1024 + col) = v;
                } else {
                    const int orow = rbase + bm + rl;
                    float2 v = make_float2(c0, c1);
                    *reinterpret_cast<float2*>(outf + (size_t)orow * 1024 + col) = v;
                }
            }
}

// ---------------------------------------------------------------------------
// combine: out[t] += w1*rout[slot1] + w2*rout[slot2]
// ---------------------------------------------------------------------------
__global__ void k_combine(float* __restrict__ out) {
    const int t = blockIdx.x;
    const int e1 = g_sel_e[t * 2],     p1 = g_sel_p[t * 2];
    const int e2 = g_sel_e[t * 2 + 1], p2 = g_sel_p[t * 2 + 1];
    const float w1 = g_sel_w[t * 2], w2 = g_sel_w[t * 2 + 1];
    const float* r1 = g_rout + (size_t)(g_base[e1] + p1) * 1024;
    const float* r2 = g_rout + (size_t)(g_base[e2] + p2) * 1024;
    float* o = out + (size_t)t * 1024;
#pragma unroll
    for (int k = 0; k < 2; k++) {
        const int j = (threadIdx.x + k * 128) * 4;
        const float4 a = *(const float4*)(r1 + j);
        const float4 b = *(const float4*)(r2 + j);
        float4 v = *(float4*)(o + j);
        v.x += w1 * a.x + w2 * b.x; v.y += w1 * a.y + w2 * b.y;
        v.z += w1 * a.z + w2 * b.z; v.w += w1 * a.w + w2 * b.w;
        *(float4*)(o + j) = v;
    }
}

// ---------------------------------------------------------------------------
// launch
// ---------------------------------------------------------------------------
extern "C" void kernel_launch(void* const* d_in, const int* in_sizes, int n_in,
                              void* d_out, int out_size)
{
    const float* X  = (const float*)d_in[0];
    const float* RW = (const float*)d_in[1];
    const float* SG = (const float*)d_in[2];
    const float* SU = (const float*)d_in[3];
    const float* SD = (const float*)d_in[4];
    const float* EG = (const float*)d_in[5];
    const float* EU = (const float*)d_in[6];
    const float* ED = (const float*)d_in[7];
    float* out = (float*)d_out;

    static bool once = false;
    if (!once) {
        cudaFuncSetAttribute(k_gateup<0>, cudaFuncAttributeMaxDynamicSharedMemorySize, GU_SMEM);
        cudaFuncSetAttribute(k_gateup<1>, cudaFuncAttributeMaxDynamicSharedMemorySize, GU_SMEM);
        cudaFuncSetAttribute(k_down<0,0>, cudaFuncAttributeMaxDynamicSharedMemorySize, DN_SMEM);
        cudaFuncSetAttribute(k_down<1,1>, cudaFuncAttributeMaxDynamicSharedMemorySize, DN_SMEM);
        once = true;
    }

    bf16 *xc, *wsg, *wsu, *wsd, *weg, *weu, *wed, *hids, *hidr;
    float *rout;
    cudaGetSymbolAddress((void**)&xc,   g_xc);
    cudaGetSymbolAddress((void**)&wsg,  g_wsg);
    cudaGetSymbolAddress((void**)&wsu,  g_wsu);
    cudaGetSymbolAddress((void**)&wsd,  g_wsd);
    cudaGetSymbolAddress((void**)&weg,  g_weg);
    cudaGetSymbolAddress((void**)&weu,  g_weu);
    cudaGetSymbolAddress((void**)&wed,  g_wed);
    cudaGetSymbolAddress((void**)&hids, g_hid_s);
    cudaGetSymbolAddress((void**)&hidr, g_hid_r);
    cudaGetSymbolAddress((void**)&rout, g_rout);

    k_init<<<1, 32>>>();
    k_convx<<<2048, 256>>>(X);
    k_convw<<<dim3(32, 32, 1),  256>>>(SG, wsg);
    k_convw<<<dim3(32, 32, 1),  256>>>(SU, wsu);
    k_convw<<<dim3(32, 32, 1),  256>>>(SD, wsd);
    k_convw<<<dim3(32, 32, NE), 256>>>(EG, weg);
    k_convw<<<dim3(32, 32, NE), 256>>>(EU, weu);
    k_convw<<<dim3(32, 32, NE), 256>>>(ED, wed);

    k_router<<<1024, 128>>>(X, RW);
    k_offsets<<<1, 32>>>();

    // fused gate+up (+SwiGLU): dense -> hid_s, gathered -> hid_r
    k_gateup<0><<<dim3(8, 32),     512, GU_SMEM>>>(xc, wsg, wsu, hids);
    k_gateup<1><<<dim3(8, 32, NE), 512, GU_SMEM>>>(xc, weg, weu, hidr);

    // down: dense writes out = X + C; routed writes rout
    k_down<0,0><<<dim3(8, 32),     256, DN_SMEM>>>(hids, wsd, X, out);
    k_down<1,1><<<dim3(8, 32, NE), 256, DN_SMEM>>>(hidr, wed, nullptr, rout);

    k_combine<<<T_TOK, 128>>>(out);
}

// round 6
// speedup vs baseline: 2.8796x; 1.0034x over previous
#include <cuda_runtime.h>
#include <cuda_bf16.h>
#include <math.h>
#include <stdint.h>

// ===========================================================================
// TinyMoE via base-ISA tensor ops (mma.sync bf16, ldmatrix, cp.async).
// 3-term hi/lo bf16 split GEMMs, fp32 accumulation.
// R6: single fused weight-conversion launch (64x64 tiles), merged
//     dense+routed GEMM launches, __expf epilogue.
// ===========================================================================

#define T_TOK 4096
#define HD    1024
#define NE    8
#define RPAD  10240

using bf16 = __nv_bfloat16;

// ---------------- device scratch -------------------------------------------
__device__ bf16  g_xc   [(size_t)T_TOK * 2048];      // X hi|lo
__device__ bf16  g_wsg  [(size_t)1024 * 2048];       // shared gate^T hi|lo [n][k]
__device__ bf16  g_wsu  [(size_t)1024 * 2048];
__device__ bf16  g_wsd  [(size_t)1024 * 2048];
__device__ bf16  g_weg  [(size_t)NE * 1024 * 2048];
__device__ bf16  g_weu  [(size_t)NE * 1024 * 2048];
__device__ bf16  g_wed  [(size_t)NE * 1024 * 2048];
__device__ bf16  g_hid_s[(size_t)T_TOK * 2048];      // shared hidden hi|lo
__device__ bf16  g_hid_r[(size_t)RPAD * 2048];       // routed hidden hi|lo
__device__ float g_rout [(size_t)RPAD * 1024];       // routed down output
__device__ int   g_cnt[NE];
__device__ int   g_base[NE];
__device__ int   g_tok[NE][T_TOK];
__device__ int   g_sel_e[T_TOK * 2];
__device__ int   g_sel_p[T_TOK * 2];
__device__ float g_sel_w[T_TOK * 2];

// ---------------- asm helpers (base ISA only) ------------------------------
__device__ __forceinline__ uint32_t s2u(const void* p) {
    uint32_t a;
    asm("{ .reg .u64 t; cvta.to.shared.u64 t, %1; cvt.u32.u64 %0, t; }" : "=r"(a) : "l"(p));
    return a;
}
__device__ __forceinline__ void cp16(uint32_t dst, const void* src) {
    asm volatile("cp.async.cg.shared.global [%0], [%1], 16;" :: "r"(dst), "l"(src));
}
__device__ __forceinline__ void cp_commit() {
    asm volatile("cp.async.commit_group;");
}
__device__ __forceinline__ void cp_wait2() {
    asm volatile("cp.async.wait_group 2;");
}
__device__ __forceinline__ void ldsm4(uint32_t* r, uint32_t addr) {
    asm volatile("ldmatrix.sync.aligned.m8n8.x4.shared.b16 {%0,%1,%2,%3}, [%4];"
        : "=r"(r[0]), "=r"(r[1]), "=r"(r[2]), "=r"(r[3]) : "r"(addr));
}
__device__ __forceinline__ void mma_bf16(float* c, const uint32_t* a, const uint32_t* b) {
    asm volatile(
        "mma.sync.aligned.m16n8k16.row.col.f32.bf16.bf16.f32 "
        "{%0,%1,%2,%3}, {%4,%5,%6,%7}, {%8,%9}, {%0,%1,%2,%3};"
        : "+f"(c[0]), "+f"(c[1]), "+f"(c[2]), "+f"(c[3])
        : "r"(a[0]), "r"(a[1]), "r"(a[2]), "r"(a[3]), "r"(b[0]), "r"(b[1]));
}
__device__ __forceinline__ void hilo2(float a, float b, uint32_t& hp, uint32_t& lp) {
    bf16 h0 = __float2bfloat16(a), h1 = __float2bfloat16(b);
    bf16 l0 = __float2bfloat16(a - __bfloat162float(h0));
    bf16 l1 = __float2bfloat16(b - __bfloat162float(h1));
    hp = (uint32_t)*(uint16_t*)&h0 | ((uint32_t)*(uint16_t*)&h1 << 16);
    lp = (uint32_t)*(uint16_t*)&l0 | ((uint32_t)*(uint16_t*)&l1 << 16);
}

// ---------------------------------------------------------------------------
// init / conversions / router
// ---------------------------------------------------------------------------
__global__ void k_init() { if (threadIdx.x < NE) g_cnt[threadIdx.x] = 0; }

// X fp32 [t][1024] -> g_xc [t][2048] hi|lo, 16B stores
__global__ void k_convx(const float* __restrict__ X) {
    const int idx = blockIdx.x * blockDim.x + threadIdx.x;   // 524288
    const int t = idx >> 7, c = (idx & 127) * 8;
    const float4 v0 = *reinterpret_cast<const float4*>(X + (size_t)t * 1024 + c);
    const float4 v1 = *reinterpret_cast<const float4*>(X + (size_t)t * 1024 + c + 4);
    uint4 hv, lv;
    hilo2(v0.x, v0.y, hv.x, lv.x);
    hilo2(v0.z, v0.w, hv.y, lv.y);
    hilo2(v1.x, v1.y, hv.z, lv.z);
    hilo2(v1.z, v1.w, hv.w, lv.w);
    *reinterpret_cast<uint4*>(g_xc + (size_t)t * 2048 + c) = hv;
    *reinterpret_cast<uint4*>(g_xc + (size_t)t * 2048 + 1024 + c) = lv;
}

// ALL weight matrices in one launch. 64x64 fp32 tile -> transposed hi|lo bf16.
// z: 0=SG 1=SU 2=SD, 3..10=EG[e], 11..18=EU[e], 19..26=ED[e]
__global__ void __launch_bounds__(256)
k_convw(const float* __restrict__ SG, const float* __restrict__ SU,
        const float* __restrict__ SD, const float* __restrict__ EG,
        const float* __restrict__ EU, const float* __restrict__ ED,
        bf16* __restrict__ wsg, bf16* __restrict__ wsu, bf16* __restrict__ wsd,
        bf16* __restrict__ weg, bf16* __restrict__ weu, bf16* __restrict__ wed)
{
    __shared__ float ts[64][65];
    const int z = blockIdx.z;
    const float* src;
    bf16* dst;
    if      (z == 0) { src = SG; dst = wsg; }
    else if (z == 1) { src = SU; dst = wsu; }
    else if (z == 2) { src = SD; dst = wsd; }
    else if (z < 11) { src = EG + (size_t)(z - 3)  * 1048576; dst = weg + (size_t)(z - 3)  * 2097152; }
    else if (z < 19) { src = EU + (size_t)(z - 11) * 1048576; dst = weu + (size_t)(z - 11) * 2097152; }
    else             { src = ED + (size_t)(z - 19) * 1048576; dst = wed + (size_t)(z - 19) * 2097152; }

    const int k0 = blockIdx.y * 64, n0 = blockIdx.x * 64;
    const int tid = threadIdx.x;

    // load 64x64 fp32 tile (each thread: 4 float4)
    {
        const int kk = tid >> 4, cc = (tid & 15) * 4;
#pragma unroll
        for (int i = 0; i < 4; i++) {
            const float4 v = *reinterpret_cast<const float4*>(
                src + (size_t)(k0 + kk + i * 16) * 1024 + n0 + cc);
            ts[kk + i * 16][cc] = v.x; ts[kk + i * 16][cc + 1] = v.y;
            ts[kk + i * 16][cc + 2] = v.z; ts[kk + i * 16][cc + 3] = v.w;
        }
    }
    __syncthreads();

    // each thread: one n-row, 16 consecutive k -> 32B hi + 32B lo stores
    const int nl = tid >> 2, kq = (tid & 3) * 16;
    uint4 hv0, hv1, lv0, lv1;
    hilo2(ts[kq +  0][nl], ts[kq +  1][nl], hv0.x, lv0.x);
    hilo2(ts[kq +  2][nl], ts[kq +  3][nl], hv0.y, lv0.y);
    hilo2(ts[kq +  4][nl], ts[kq +  5][nl], hv0.z, lv0.z);
    hilo2(ts[kq +  6][nl], ts[kq +  7][nl], hv0.w, lv0.w);
    hilo2(ts[kq +  8][nl], ts[kq +  9][nl], hv1.x, lv1.x);
    hilo2(ts[kq + 10][nl], ts[kq + 11][nl], hv1.y, lv1.y);
    hilo2(ts[kq + 12][nl], ts[kq + 13][nl], hv1.z, lv1.z);
    hilo2(ts[kq + 14][nl], ts[kq + 15][nl], hv1.w, lv1.w);
    bf16* drow = dst + (size_t)(n0 + nl) * 2048 + k0 + kq;
    *reinterpret_cast<uint4*>(drow) = hv0;
    *reinterpret_cast<uint4*>(drow + 8) = hv1;
    *reinterpret_cast<uint4*>(drow + 1024) = lv0;
    *reinterpret_cast<uint4*>(drow + 1032) = lv1;
}

__global__ void k_router(const float* __restrict__ X, const float* __restrict__ RW) {
    const int t = (blockIdx.x * blockDim.x + threadIdx.x) >> 5;
    const int lane = threadIdx.x & 31;
    if (t >= T_TOK) return;
    const float* xr = X + (size_t)t * HD;
    float acc[NE];
#pragma unroll
    for (int e = 0; e < NE; e++) acc[e] = 0.f;
    for (int h = lane; h < HD; h += 32) {
        const float xv = xr[h];
#pragma unroll
        for (int e = 0; e < NE; e++) acc[e] += xv * RW[e * HD + h];
    }
#pragma unroll
    for (int e = 0; e < NE; e++)
#pragma unroll
        for (int off = 16; off > 0; off >>= 1)
            acc[e] += __shfl_down_sync(0xffffffffu, acc[e], off);
    if (lane == 0) {
        float m = acc[0];
#pragma unroll
        for (int e = 1; e < NE; e++) m = fmaxf(m, acc[e]);
        float p[NE], s = 0.f;
#pragma unroll
        for (int e = 0; e < NE; e++) { p[e] = expf(acc[e] - m); s += p[e]; }
        const float inv = 1.f / s;
#pragma unroll
        for (int e = 0; e < NE; e++) p[e] *= inv;
        int i1 = 0; float b1 = p[0];
#pragma unroll
        for (int e = 1; e < NE; e++) if (p[e] > b1) { b1 = p[e]; i1 = e; }
        int i2 = -1; float b2 = -1.f;
#pragma unroll
        for (int e = 0; e < NE; e++) if (e != i1 && p[e] > b2) { b2 = p[e]; i2 = e; }
        int pos = atomicAdd(&g_cnt[i1], 1);
        g_tok[i1][pos] = t;
        g_sel_e[t * 2] = i1; g_sel_p[t * 2] = pos; g_sel_w[t * 2] = b1;
        pos = atomicAdd(&g_cnt[i2], 1);
        g_tok[i2][pos] = t;
        g_sel_e[t * 2 + 1] = i2; g_sel_p[t * 2 + 1] = pos; g_sel_w[t * 2 + 1] = b2;
    }
}

__global__ void k_offsets() {
    if (threadIdx.x == 0) {
        int b = 0;
        for (int e = 0; e < NE; e++) { g_base[e] = b; b += (g_cnt[e] + 127) & ~127; }
    }
}

// ---------------------------------------------------------------------------
// Fused gate+up GEMM + SwiGLU, merged dense (z=0) + routed (z=1..8).
// 512 threads, warp tile 32x32 per matrix, 3-stage cp.async pipeline.
// ---------------------------------------------------------------------------
#define GU_STG   49152
#define GU_SMEM  (3 * GU_STG)

__global__ void __launch_bounds__(512)
k_gateup(const bf16* __restrict__ A, const bf16* __restrict__ Bg_all,
         const bf16* __restrict__ Bu_all, const bf16* __restrict__ Beg,
         const bf16* __restrict__ Beu, bf16* __restrict__ Hs, bf16* __restrict__ Hr)
{
    extern __shared__ char smraw[];
    const uint32_t smu = s2u(smraw);
    const int tid = threadIdx.x;
    const int bn = blockIdx.x * 128;
    const int bm = blockIdx.y * 128;
    const int z = blockIdx.z;

    const bf16 *Bg, *Bu;
    bf16* Hout;
    const int* toks = nullptr;
    int cnt = 0;
    if (z == 0) {
        Bg = Bg_all; Bu = Bu_all; Hout = Hs;
    } else {
        const int e = z - 1;
        cnt = g_cnt[e];
        if (bm >= cnt) return;
        toks = g_tok[e];
        Bg = Beg + (size_t)e * 1024 * 2048;
        Bu = Beu + (size_t)e * 1024 * 2048;
        Hout = Hr + (size_t)g_base[e] * 2048;
    }

    const int lr = tid >> 3;
    const int lc = tid & 7;
    const int coff = (lc < 4) ? lc * 8 : 1024 + (lc - 4) * 8;

    const bf16 *arp[2], *bgp[2], *bup[2];
    uint32_t dA[2], dBg[2], dBu[2];
#pragma unroll
    for (int i = 0; i < 2; i++) {
        const int r = lr + 64 * i;
        int arow;
        if (z != 0) {
            const int slot = bm + r;
            arow = toks[slot < cnt - 1 ? slot : cnt - 1];
        } else {
            arow = bm + r;
        }
        arp[i] = A + (size_t)arow * 2048 + coff;
        bgp[i] = Bg + (size_t)(bn + r) * 2048 + coff;
        bup[i] = Bu + (size_t)(bn + r) * 2048 + coff;
        const uint32_t o = (uint32_t)(r * 128 + ((lc ^ (r & 7)) << 4));
        dA[i] = o; dBg[i] = 16384u + o; dBu[i] = 32768u + o;
    }

    const int lane = tid & 31, w = tid >> 5;
    const int m0 = (w & 3) * 32, n0 = (w >> 2) * 32;

    float accG[2][4][4], accU[2][4][4];
#pragma unroll
    for (int mf = 0; mf < 2; mf++)
#pragma unroll
        for (int nf = 0; nf < 4; nf++)
#pragma unroll
            for (int j = 0; j < 4; j++) { accG[mf][nf][j] = 0.f; accU[mf][nf][j] = 0.f; }

#pragma unroll
    for (int st = 0; st < 2; st++) {
        const uint32_t sa = smu + st * GU_STG;
        const int kb = st * 32;
#pragma unroll
        for (int i = 0; i < 2; i++) {
            cp16(sa + dA[i],  arp[i] + kb);
            cp16(sa + dBg[i], bgp[i] + kb);
            cp16(sa + dBu[i], bup[i] + kb);
        }
        cp_commit();
    }

    const int ar_ = lane & 15;
    const int ac_ = lane >> 4;
    const int br_ = (lane & 7) + ((lane >> 4) << 3);
    const int bc_ = (lane >> 3) & 1;

    int stw = 2;
    for (int it = 0; it < 32; ++it) {
        if (it + 2 < 32) {
            const uint32_t sa = smu + stw * GU_STG;
            const int kb = (it + 2) * 32;
#pragma unroll
            for (int i = 0; i < 2; i++) {
                cp16(sa + dA[i],  arp[i] + kb);
                cp16(sa + dBg[i], bgp[i] + kb);
                cp16(sa + dBu[i], bup[i] + kb);
            }
            stw = (stw + 1) == 3 ? 0 : stw + 1;
        }
        cp_commit();
        cp_wait2();
        __syncthreads();

        const uint32_t sa = smu + (it % 3) * GU_STG;
        const uint32_t sg = sa + 16384u, su = sa + 32768u;
#pragma unroll
        for (int s = 0; s < 2; s++) {
            uint32_t ah[2][4], al[2][4];
#pragma unroll
            for (int mf = 0; mf < 2; mf++) {
                const int r = m0 + mf * 16 + ar_;
                const int c = s * 2 + ac_;
                ldsm4(ah[mf], sa + r * 128 + (((c)     ^ (r & 7)) << 4));
                ldsm4(al[mf], sa + r * 128 + (((c + 4) ^ (r & 7)) << 4));
            }
            {
                uint32_t bh[2][4], bl[2][4];
#pragma unroll
                for (int bi = 0; bi < 2; bi++) {
                    const int nr = n0 + bi * 16 + br_;
                    const int c = s * 2 + bc_;
                    ldsm4(bh[bi], sg + nr * 128 + (((c)     ^ (nr & 7)) << 4));
                    ldsm4(bl[bi], sg + nr * 128 + (((c + 4) ^ (nr & 7)) << 4));
                }
#pragma unroll
                for (int mf = 0; mf < 2; mf++)
#pragma unroll
                    for (int nf = 0; nf < 4; nf++) {
                        const uint32_t* ph = &bh[nf >> 1][(nf & 1) * 2];
                        const uint32_t* pl = &bl[nf >> 1][(nf & 1) * 2];
                        mma_bf16(accG[mf][nf], ah[mf], ph);
                        mma_bf16(accG[mf][nf], al[mf], ph);
                        mma_bf16(accG[mf][nf], ah[mf], pl);
                    }
            }
            {
                uint32_t bh[2][4], bl[2][4];
#pragma unroll
                for (int bi = 0; bi < 2; bi++) {
                    const int nr = n0 + bi * 16 + br_;
                    const int c = s * 2 + bc_;
                    ldsm4(bh[bi], su + nr * 128 + (((c)     ^ (nr & 7)) << 4));
                    ldsm4(bl[bi], su + nr * 128 + (((c + 4) ^ (nr & 7)) << 4));
                }
#pragma unroll
                for (int mf = 0; mf < 2; mf++)
#pragma unroll
                    for (int nf = 0; nf < 4; nf++) {
                        const uint32_t* ph = &bh[nf >> 1][(nf & 1) * 2];
                        const uint32_t* pl = &bl[nf >> 1][(nf & 1) * 2];
                        mma_bf16(accU[mf][nf], ah[mf], ph);
                        mma_bf16(accU[mf][nf], al[mf], ph);
                        mma_bf16(accU[mf][nf], ah[mf], pl);
                    }
            }
        }
        __syncthreads();
    }

    const int mr = lane >> 2, nc2 = (lane & 3) * 2;
#pragma unroll
    for (int mf = 0; mf < 2; mf++)
#pragma unroll
        for (int nf = 0; nf < 4; nf++)
#pragma unroll
            for (int h = 0; h < 2; h++) {
                const int rl = m0 + mf * 16 + mr + h * 8;
                const int col = bn + n0 + nf * 8 + nc2;
                const float g0 = accG[mf][nf][h * 2], g1 = accG[mf][nf][h * 2 + 1];
                const float u0 = accU[mf][nf][h * 2], u1 = accU[mf][nf][h * 2 + 1];
                const float v0 = u0 / (1.f + __expf(-g0));
                const float v1 = u1 / (1.f + __expf(-g1));
                uint32_t hp, lp;
                hilo2(v0, v1, hp, lp);
                bf16* hrow = Hout + (size_t)(bm + rl) * 2048 + col;
                *reinterpret_cast<uint32_t*>(hrow) = hp;
                *reinterpret_cast<uint32_t*>(hrow + 1024) = lp;
            }
}

// ---------------------------------------------------------------------------
// Down GEMM merged: z=0 dense (out = X + C), z=1..8 routed (g_rout = C).
// 256 threads, warp tile 32x64, 3-stage pipeline.
// ---------------------------------------------------------------------------
#define DN_STG   32768
#define DN_SMEM  (3 * DN_STG)

__global__ void __launch_bounds__(256)
k_down(const bf16* __restrict__ As, const bf16* __restrict__ Ar,
       const bf16* __restrict__ Bs, const bf16* __restrict__ Be,
       const float* __restrict__ X, float* __restrict__ out, float* __restrict__ rout)
{
    extern __shared__ char smraw[];
    const uint32_t smu = s2u(smraw);
    const int tid = threadIdx.x;
    const int bn = blockIdx.x * 128;
    const int bm = blockIdx.y * 128;
    const int z = blockIdx.z;

    const bf16 *A, *B;
    int rbase = 0;
    if (z == 0) {
        A = As; B = Bs;
    } else {
        const int e = z - 1;
        if (bm >= g_cnt[e]) return;
        rbase = g_base[e];
        A = Ar; B = Be + (size_t)e * 1024 * 2048;
    }

    const int lr = tid >> 3;
    const int lc = tid & 7;
    const int coff = (lc < 4) ? lc * 8 : 1024 + (lc - 4) * 8;

    const bf16 *arp[4], *brp[4];
    uint32_t dA[4], dB[4];
#pragma unroll
    for (int i = 0; i < 4; i++) {
        const int r = lr + 32 * i;
        arp[i] = A + (size_t)(rbase + bm + r) * 2048 + coff;
        brp[i] = B + (size_t)(bn + r) * 2048 + coff;
        const uint32_t o = (uint32_t)(r * 128 + ((lc ^ (r & 7)) << 4));
        dA[i] = o; dB[i] = 16384u + o;
    }

    const int lane = tid & 31, w = tid >> 5;
    const int m0 = (w & 3) * 32, n0 = (w >> 2) * 64;

    float acc[2][8][4];
#pragma unroll
    for (int mf = 0; mf < 2; mf++)
#pragma unroll
        for (int nf = 0; nf < 8; nf++)
#pragma unroll
            for (int j = 0; j < 4; j++) acc[mf][nf][j] = 0.f;

#pragma unroll
    for (int st = 0; st < 2; st++) {
        const uint32_t sa = smu + st * DN_STG;
        const int kb = st * 32;
#pragma unroll
        for (int i = 0; i < 4; i++) { cp16(sa + dA[i], arp[i] + kb); cp16(sa + dB[i], brp[i] + kb); }
        cp_commit();
    }

    const int ar_ = lane & 15;
    const int ac_ = lane >> 4;
    const int br_ = (lane & 7) + ((lane >> 4) << 3);
    const int bc_ = (lane >> 3) & 1;

    int stw = 2;
    for (int it = 0; it < 32; ++it) {
        if (it + 2 < 32) {
            const uint32_t sa = smu + stw * DN_STG;
            const int kb = (it + 2) * 32;
#pragma unroll
            for (int i = 0; i < 4; i++) { cp16(sa + dA[i], arp[i] + kb); cp16(sa + dB[i], brp[i] + kb); }
            stw = (stw + 1) == 3 ? 0 : stw + 1;
        }
        cp_commit();
        cp_wait2();
        __syncthreads();

        const uint32_t sa = smu + (it % 3) * DN_STG;
        const uint32_t sb = sa + 16384u;
#pragma unroll
        for (int s = 0; s < 2; s++) {
            uint32_t ah[2][4], al[2][4], bh[4][4], bl[4][4];
#pragma unroll
            for (int mf = 0; mf < 2; mf++) {
                const int r = m0 + mf * 16 + ar_;
                const int c = s * 2 + ac_;
                ldsm4(ah[mf], sa + r * 128 + (((c)     ^ (r & 7)) << 4));
                ldsm4(al[mf], sa + r * 128 + (((c + 4) ^ (r & 7)) << 4));
            }
#pragma unroll
            for (int bi = 0; bi < 4; bi++) {
                const int nr = n0 + bi * 16 + br_;
                const int c = s * 2 + bc_;
                ldsm4(bh[bi], sb + nr * 128 + (((c)     ^ (nr & 7)) << 4));
                ldsm4(bl[bi], sb + nr * 128 + (((c + 4) ^ (nr & 7)) << 4));
            }
#pragma unroll
            for (int mf = 0; mf < 2; mf++)
#pragma unroll
                for (int nf = 0; nf < 8; nf++) {
                    const uint32_t* ph = &bh[nf >> 1][(nf & 1) * 2];
                    const uint32_t* pl = &bl[nf >> 1][(nf & 1) * 2];
                    mma_bf16(acc[mf][nf], ah[mf], ph);
                    mma_bf16(acc[mf][nf], al[mf], ph);
                    mma_bf16(acc[mf][nf], ah[mf], pl);
                }
        }
        __syncthreads();
    }

    const int mr = lane >> 2, nc2 = (lane & 3) * 2;
#pragma unroll
    for (int mf = 0; mf < 2; mf++)
#pragma unroll
        for (int nf = 0; nf < 8; nf++)
#pragma unroll
            for (int h = 0; h < 2; h++) {
                const int rl = m0 + mf * 16 + mr + h * 8;
                const int col = bn + n0 + nf * 8 + nc2;
                const float c0 = acc[mf][nf][h * 2], c1 = acc[mf][nf][h * 2 + 1];
                if (z == 0) {
                    const int t = bm + rl;
                    const float2 rv = *reinterpret_cast<const float2*>(X + (size_t)t * 1024 + col);
                    float2 v = make_float2(rv.x + c0, rv.y + c1);
                    *reinterpret_cast<float2*>(out + (size_t)t * 1024 + col) = v;
                } else {
                    const int orow = rbase + bm + rl;
                    float2 v = make_float2(c0, c1);
                    *reinterpret_cast<float2*>(rout + (size_t)orow * 1024 + col) = v;
                }
            }
}

// ---------------------------------------------------------------------------
// combine: out[t] += w1*rout[slot1] + w2*rout[slot2]
// ---------------------------------------------------------------------------
__global__ void k_combine(float* __restrict__ out) {
    const int t = blockIdx.x;
    const int e1 = g_sel_e[t * 2],     p1 = g_sel_p[t * 2];
    const int e2 = g_sel_e[t * 2 + 1], p2 = g_sel_p[t * 2 + 1];
    const float w1 = g_sel_w[t * 2], w2 = g_sel_w[t * 2 + 1];
    const float* r1 = g_rout + (size_t)(g_base[e1] + p1) * 1024;
    const float* r2 = g_rout + (size_t)(g_base[e2] + p2) * 1024;
    float* o = out + (size_t)t * 1024;
#pragma unroll
    for (int k = 0; k < 2; k++) {
        const int j = (threadIdx.x + k * 128) * 4;
        const float4 a = *(const float4*)(r1 + j);
        const float4 b = *(const float4*)(r2 + j);
        float4 v = *(float4*)(o + j);
        v.x += w1 * a.x + w2 * b.x; v.y += w1 * a.y + w2 * b.y;
        v.z += w1 * a.z + w2 * b.z; v.w += w1 * a.w + w2 * b.w;
        *(float4*)(o + j) = v;
    }
}

// ---------------------------------------------------------------------------
// launch
// ---------------------------------------------------------------------------
extern "C" void kernel_launch(void* const* d_in, const int* in_sizes, int n_in,
                              void* d_out, int out_size)
{
    const float* X  = (const float*)d_in[0];
    const float* RW = (const float*)d_in[1];
    const float* SG = (const float*)d_in[2];
    const float* SU = (const float*)d_in[3];
    const float* SD = (const float*)d_in[4];
    const float* EG = (const float*)d_in[5];
    const float* EU = (const float*)d_in[6];
    const float* ED = (const float*)d_in[7];
    float* out = (float*)d_out;

    static bool once = false;
    if (!once) {
        cudaFuncSetAttribute(k_gateup, cudaFuncAttributeMaxDynamicSharedMemorySize, GU_SMEM);
        cudaFuncSetAttribute(k_down,   cudaFuncAttributeMaxDynamicSharedMemorySize, DN_SMEM);
        once = true;
    }

    bf16 *xc, *wsg, *wsu, *wsd, *weg, *weu, *wed, *hids, *hidr;
    float *rout;
    cudaGetSymbolAddress((void**)&xc,   g_xc);
    cudaGetSymbolAddress((void**)&wsg,  g_wsg);
    cudaGetSymbolAddress((void**)&wsu,  g_wsu);
    cudaGetSymbolAddress((void**)&wsd,  g_wsd);
    cudaGetSymbolAddress((void**)&weg,  g_weg);
    cudaGetSymbolAddress((void**)&weu,  g_weu);
    cudaGetSymbolAddress((void**)&wed,  g_wed);
    cudaGetSymbolAddress((void**)&hids, g_hid_s);
    cudaGetSymbolAddress((void**)&hidr, g_hid_r);
    cudaGetSymbolAddress((void**)&rout, g_rout);

    k_init<<<1, 32>>>();
    k_router<<<1024, 128>>>(X, RW);
    k_offsets<<<1, 32>>>();
    k_convx<<<2048, 256>>>(X);
    k_convw<<<dim3(16, 16, 27), 256>>>(SG, SU, SD, EG, EU, ED,
                                       wsg, wsu, wsd, weg, weu, wed);

    k_gateup<<<dim3(8, 32, 9), 512, GU_SMEM>>>(xc, wsg, wsu, weg, weu, hids, hidr);
    k_down  <<<dim3(8, 32, 9), 256, DN_SMEM>>>(hids, hidr, wsd, wed, X, out, rout);

    k_combine<<<T_TOK, 128>>>(out);
}

// round 7
// speedup vs baseline: 7.0832x; 2.4598x over previous
#include <cuda_runtime.h>
#include <cuda_fp16.h>
#include <math.h>
#include <stdint.h>

// ===========================================================================
// TinyMoE via base-ISA tensor ops. R7: single-fp16 GEMMs (exact fp16 products,
// fp32 accumulate). T=4096, H=I=1024, E=8, top-2 routing, route-then-compute.
// ===========================================================================

#define T_TOK 4096
#define HD    1024
#define NE    8
#define RPAD  10240

using f16 = __half;

// ---------------- device scratch -------------------------------------------
__device__ f16   g_xc   [(size_t)T_TOK * 1024];      // X fp16
__device__ f16   g_wsg  [(size_t)1024 * 1024];       // shared gate^T [n][k]
__device__ f16   g_wsu  [(size_t)1024 * 1024];
__device__ f16   g_wsd  [(size_t)1024 * 1024];
__device__ f16   g_weg  [(size_t)NE * 1024 * 1024];
__device__ f16   g_weu  [(size_t)NE * 1024 * 1024];
__device__ f16   g_wed  [(size_t)NE * 1024 * 1024];
__device__ f16   g_hid_s[(size_t)T_TOK * 1024];      // shared hidden fp16
__device__ f16   g_hid_r[(size_t)RPAD * 1024];       // routed hidden fp16
__device__ float g_rout [(size_t)RPAD * 1024];       // routed down output
__device__ int   g_cnt[NE];
__device__ int   g_base[NE];
__device__ int   g_tok[NE][T_TOK];
__device__ int   g_sel_e[T_TOK * 2];
__device__ int   g_sel_p[T_TOK * 2];
__device__ float g_sel_w[T_TOK * 2];

// ---------------- asm helpers (base ISA only) ------------------------------
__device__ __forceinline__ uint32_t s2u(const void* p) {
    uint32_t a;
    asm("{ .reg .u64 t; cvta.to.shared.u64 t, %1; cvt.u32.u64 %0, t; }" : "=r"(a) : "l"(p));
    return a;
}
__device__ __forceinline__ void cp16(uint32_t dst, const void* src) {
    asm volatile("cp.async.cg.shared.global [%0], [%1], 16;" :: "r"(dst), "l"(src));
}
__device__ __forceinline__ void cp_commit() {
    asm volatile("cp.async.commit_group;");
}
__device__ __forceinline__ void cp_wait2() {
    asm volatile("cp.async.wait_group 2;");
}
__device__ __forceinline__ void ldsm4(uint32_t* r, uint32_t addr) {
    asm volatile("ldmatrix.sync.aligned.m8n8.x4.shared.b16 {%0,%1,%2,%3}, [%4];"
        : "=r"(r[0]), "=r"(r[1]), "=r"(r[2]), "=r"(r[3]) : "r"(addr));
}
__device__ __forceinline__ void mma_f16(float* c, const uint32_t* a, const uint32_t* b) {
    asm volatile(
        "mma.sync.aligned.m16n8k16.row.col.f32.f16.f16.f32 "
        "{%0,%1,%2,%3}, {%4,%5,%6,%7}, {%8,%9}, {%0,%1,%2,%3};"
        : "+f"(c[0]), "+f"(c[1]), "+f"(c[2]), "+f"(c[3])
        : "r"(a[0]), "r"(a[1]), "r"(a[2]), "r"(a[3]), "r"(b[0]), "r"(b[1]));
}
__device__ __forceinline__ uint32_t packh2(float a, float b) {
    f16 h0 = __float2half_rn(a), h1 = __float2half_rn(b);
    return (uint32_t)*(uint16_t*)&h0 | ((uint32_t)*(uint16_t*)&h1 << 16);
}

// ---------------------------------------------------------------------------
// init / conversions / router
// ---------------------------------------------------------------------------
__global__ void k_init() { if (threadIdx.x < NE) g_cnt[threadIdx.x] = 0; }

// X fp32 [t][1024] -> g_xc fp16, 16B stores
__global__ void k_convx(const float* __restrict__ X) {
    const int idx = blockIdx.x * blockDim.x + threadIdx.x;   // 524288
    const int t = idx >> 7, c = (idx & 127) * 8;
    const float4 v0 = *reinterpret_cast<const float4*>(X + (size_t)t * 1024 + c);
    const float4 v1 = *reinterpret_cast<const float4*>(X + (size_t)t * 1024 + c + 4);
    uint4 hv;
    hv.x = packh2(v0.x, v0.y); hv.y = packh2(v0.z, v0.w);
    hv.z = packh2(v1.x, v1.y); hv.w = packh2(v1.z, v1.w);
    *reinterpret_cast<uint4*>(g_xc + (size_t)t * 1024 + c) = hv;
}

// ALL weight matrices, one launch. 64x64 fp32 tile -> transposed fp16.
// z: 0=SG 1=SU 2=SD, 3..10=EG[e], 11..18=EU[e], 19..26=ED[e]
__global__ void __launch_bounds__(256)
k_convw(const float* __restrict__ SG, const float* __restrict__ SU,
        const float* __restrict__ SD, const float* __restrict__ EG,
        const float* __restrict__ EU, const float* __restrict__ ED,
        f16* __restrict__ wsg, f16* __restrict__ wsu, f16* __restrict__ wsd,
        f16* __restrict__ weg, f16* __restrict__ weu, f16* __restrict__ wed)
{
    __shared__ float ts[64][65];
    const int z = blockIdx.z;
    const float* src;
    f16* dst;
    if      (z == 0) { src = SG; dst = wsg; }
    else if (z == 1) { src = SU; dst = wsu; }
    else if (z == 2) { src = SD; dst = wsd; }
    else if (z < 11) { src = EG + (size_t)(z - 3)  * 1048576; dst = weg + (size_t)(z - 3)  * 1048576; }
    else if (z < 19) { src = EU + (size_t)(z - 11) * 1048576; dst = weu + (size_t)(z - 11) * 1048576; }
    else             { src = ED + (size_t)(z - 19) * 1048576; dst = wed + (size_t)(z - 19) * 1048576; }

    const int k0 = blockIdx.y * 64, n0 = blockIdx.x * 64;
    const int tid = threadIdx.x;
    {
        const int kk = tid >> 4, cc = (tid & 15) * 4;
#pragma unroll
        for (int i = 0; i < 4; i++) {
            const float4 v = *reinterpret_cast<const float4*>(
                src + (size_t)(k0 + kk + i * 16) * 1024 + n0 + cc);
            ts[kk + i * 16][cc] = v.x; ts[kk + i * 16][cc + 1] = v.y;
            ts[kk + i * 16][cc + 2] = v.z; ts[kk + i * 16][cc + 3] = v.w;
        }
    }
    __syncthreads();
    const int nl = tid >> 2, kq = (tid & 3) * 16;
    uint4 a, b;
    a.x = packh2(ts[kq +  0][nl], ts[kq +  1][nl]);
    a.y = packh2(ts[kq +  2][nl], ts[kq +  3][nl]);
    a.z = packh2(ts[kq +  4][nl], ts[kq +  5][nl]);
    a.w = packh2(ts[kq +  6][nl], ts[kq +  7][nl]);
    b.x = packh2(ts[kq +  8][nl], ts[kq +  9][nl]);
    b.y = packh2(ts[kq + 10][nl], ts[kq + 11][nl]);
    b.z = packh2(ts[kq + 12][nl], ts[kq + 13][nl]);
    b.w = packh2(ts[kq + 14][nl], ts[kq + 15][nl]);
    f16* drow = dst + (size_t)(n0 + nl) * 1024 + k0 + kq;
    *reinterpret_cast<uint4*>(drow) = a;
    *reinterpret_cast<uint4*>(drow + 8) = b;
}

__global__ void k_router(const float* __restrict__ X, const float* __restrict__ RW) {
    const int t = (blockIdx.x * blockDim.x + threadIdx.x) >> 5;
    const int lane = threadIdx.x & 31;
    if (t >= T_TOK) return;
    const float* xr = X + (size_t)t * HD;
    float acc[NE];
#pragma unroll
    for (int e = 0; e < NE; e++) acc[e] = 0.f;
    for (int h = lane; h < HD; h += 32) {
        const float xv = xr[h];
#pragma unroll
        for (int e = 0; e < NE; e++) acc[e] += xv * RW[e * HD + h];
    }
#pragma unroll
    for (int e = 0; e < NE; e++)
#pragma unroll
        for (int off = 16; off > 0; off >>= 1)
            acc[e] += __shfl_down_sync(0xffffffffu, acc[e], off);
    if (lane == 0) {
        float m = acc[0];
#pragma unroll
        for (int e = 1; e < NE; e++) m = fmaxf(m, acc[e]);
        float p[NE], s = 0.f;
#pragma unroll
        for (int e = 0; e < NE; e++) { p[e] = expf(acc[e] - m); s += p[e]; }
        const float inv = 1.f / s;
#pragma unroll
        for (int e = 0; e < NE; e++) p[e] *= inv;
        int i1 = 0; float b1 = p[0];
#pragma unroll
        for (int e = 1; e < NE; e++) if (p[e] > b1) { b1 = p[e]; i1 = e; }
        int i2 = -1; float b2 = -1.f;
#pragma unroll
        for (int e = 0; e < NE; e++) if (e != i1 && p[e] > b2) { b2 = p[e]; i2 = e; }
        int pos = atomicAdd(&g_cnt[i1], 1);
        g_tok[i1][pos] = t;
        g_sel_e[t * 2] = i1; g_sel_p[t * 2] = pos; g_sel_w[t * 2] = b1;
        pos = atomicAdd(&g_cnt[i2], 1);
        g_tok[i2][pos] = t;
        g_sel_e[t * 2 + 1] = i2; g_sel_p[t * 2 + 1] = pos; g_sel_w[t * 2 + 1] = b2;
    }
}

__global__ void k_offsets() {
    if (threadIdx.x == 0) {
        int b = 0;
        for (int e = 0; e < NE; e++) { g_base[e] = b; b += (g_cnt[e] + 127) & ~127; }
    }
}

// ---------------------------------------------------------------------------
// Fused gate+up GEMM + SwiGLU, merged dense (z=0) + routed (z=1..8).
// 512 threads, warp tile 32x32 per matrix. BK=64, 16 iters, 3-stage pipeline.
// smem stage = A(16K) + Bg(16K) + Bu(16K); rows are 128B = 64 fp16 of K.
// ---------------------------------------------------------------------------
#define GU_STG   49152
#define GU_SMEM  (3 * GU_STG)

__global__ void __launch_bounds__(512)
k_gateup(const f16* __restrict__ A, const f16* __restrict__ Bg_all,
         const f16* __restrict__ Bu_all, const f16* __restrict__ Beg,
         const f16* __restrict__ Beu, f16* __restrict__ Hs, f16* __restrict__ Hr)
{
    extern __shared__ char smraw[];
    const uint32_t smu = s2u(smraw);
    const int tid = threadIdx.x;
    const int bn = blockIdx.x * 128;
    const int bm = blockIdx.y * 128;
    const int z = blockIdx.z;

    const f16 *Bg, *Bu;
    f16* Hout;
    const int* toks = nullptr;
    int cnt = 0;
    if (z == 0) {
        Bg = Bg_all; Bu = Bu_all; Hout = Hs;
    } else {
        const int e = z - 1;
        cnt = g_cnt[e];
        if (bm >= cnt) return;
        toks = g_tok[e];
        Bg = Beg + (size_t)e * 1048576;
        Bu = Beu + (size_t)e * 1048576;
        Hout = Hr + (size_t)g_base[e] * 1024;
    }

    // load mapping: 64 fp16 per row-stage = 8 x 16B chunks; 512 threads cover
    // (128 rows x 8 chunks) x 3 tiles with 2 rows/tile each -> 6 cp16/thread.
    const int lr = tid >> 3;        // 0..63
    const int lc = tid & 7;         // chunk
    const int coff = lc * 8;        // fp16 elems within 64-wide K slab

    const f16 *arp[2], *bgp[2], *bup[2];
    uint32_t dA[2], dBg[2], dBu[2];
#pragma unroll
    for (int i = 0; i < 2; i++) {
        const int r = lr + 64 * i;
        int arow;
        if (z != 0) {
            const int slot = bm + r;
            arow = toks[slot < cnt - 1 ? slot : cnt - 1];
        } else {
            arow = bm + r;
        }
        arp[i] = A + (size_t)arow * 1024 + coff;
        bgp[i] = Bg + (size_t)(bn + r) * 1024 + coff;
        bup[i] = Bu + (size_t)(bn + r) * 1024 + coff;
        const uint32_t o = (uint32_t)(r * 128 + ((lc ^ (r & 7)) << 4));
        dA[i] = o; dBg[i] = 16384u + o; dBu[i] = 32768u + o;
    }

    const int lane = tid & 31, w = tid >> 5;
    const int m0 = (w & 3) * 32, n0 = (w >> 2) * 32;

    float accG[2][4][4], accU[2][4][4];
#pragma unroll
    for (int mf = 0; mf < 2; mf++)
#pragma unroll
        for (int nf = 0; nf < 4; nf++)
#pragma unroll
            for (int j = 0; j < 4; j++) { accG[mf][nf][j] = 0.f; accU[mf][nf][j] = 0.f; }

#pragma unroll
    for (int st = 0; st < 2; st++) {
        const uint32_t sa = smu + st * GU_STG;
        const int kb = st * 64;
#pragma unroll
        for (int i = 0; i < 2; i++) {
            cp16(sa + dA[i],  arp[i] + kb);
            cp16(sa + dBg[i], bgp[i] + kb);
            cp16(sa + dBu[i], bup[i] + kb);
        }
        cp_commit();
    }

    const int ar_ = lane & 15;
    const int ac_ = lane >> 4;
    const int br_ = (lane & 7) + ((lane >> 4) << 3);
    const int bc_ = (lane >> 3) & 1;

    int stw = 2;
    for (int it = 0; it < 16; ++it) {
        if (it + 2 < 16) {
            const uint32_t sa = smu + stw * GU_STG;
            const int kb = (it + 2) * 64;
#pragma unroll
            for (int i = 0; i < 2; i++) {
                cp16(sa + dA[i],  arp[i] + kb);
                cp16(sa + dBg[i], bgp[i] + kb);
                cp16(sa + dBu[i], bup[i] + kb);
            }
            stw = (stw + 1) == 3 ? 0 : stw + 1;
        }
        cp_commit();
        cp_wait2();
        __syncthreads();

        const uint32_t sa = smu + (it % 3) * GU_STG;
        const uint32_t sg = sa + 16384u, su = sa + 32768u;
#pragma unroll
        for (int s = 0; s < 4; s++) {       // 4 x k16 within BK=64
            uint32_t av[2][4];
#pragma unroll
            for (int mf = 0; mf < 2; mf++) {
                const int r = m0 + mf * 16 + ar_;
                const int c = s * 2 + ac_;
                ldsm4(av[mf], sa + r * 128 + ((c ^ (r & 7)) << 4));
            }
            {
                uint32_t bv[2][4];
#pragma unroll
                for (int bi = 0; bi < 2; bi++) {
                    const int nr = n0 + bi * 16 + br_;
                    const int c = s * 2 + bc_;
                    ldsm4(bv[bi], sg + nr * 128 + ((c ^ (nr & 7)) << 4));
                }
#pragma unroll
                for (int mf = 0; mf < 2; mf++)
#pragma unroll
                    for (int nf = 0; nf < 4; nf++)
                        mma_f16(accG[mf][nf], av[mf], &bv[nf >> 1][(nf & 1) * 2]);
            }
            {
                uint32_t bv[2][4];
#pragma unroll
                for (int bi = 0; bi < 2; bi++) {
                    const int nr = n0 + bi * 16 + br_;
                    const int c = s * 2 + bc_;
                    ldsm4(bv[bi], su + nr * 128 + ((c ^ (nr & 7)) << 4));
                }
#pragma unroll
                for (int mf = 0; mf < 2; mf++)
#pragma unroll
                    for (int nf = 0; nf < 4; nf++)
                        mma_f16(accU[mf][nf], av[mf], &bv[nf >> 1][(nf & 1) * 2]);
            }
        }
        __syncthreads();
    }

    // SwiGLU epilogue -> fp16 hidden
    const int mr = lane >> 2, nc2 = (lane & 3) * 2;
#pragma unroll
    for (int mf = 0; mf < 2; mf++)
#pragma unroll
        for (int nf = 0; nf < 4; nf++)
#pragma unroll
            for (int h = 0; h < 2; h++) {
                const int rl = m0 + mf * 16 + mr + h * 8;
                const int col = bn + n0 + nf * 8 + nc2;
                const float g0 = accG[mf][nf][h * 2], g1 = accG[mf][nf][h * 2 + 1];
                const float u0 = accU[mf][nf][h * 2], u1 = accU[mf][nf][h * 2 + 1];
                const float v0 = u0 / (1.f + __expf(-g0));
                const float v1 = u1 / (1.f + __expf(-g1));
                *reinterpret_cast<uint32_t*>(Hout + (size_t)(bm + rl) * 1024 + col) =
                    packh2(v0, v1);
            }
}

// ---------------------------------------------------------------------------
// Down GEMM merged: z=0 dense (out = X + C), z=1..8 routed (g_rout = C).
// 256 threads, warp tile 32x64, BK=64, 16 iters, 3-stage pipeline.
// ---------------------------------------------------------------------------
#define DN_STG   32768
#define DN_SMEM  (3 * DN_STG)

__global__ void __launch_bounds__(256)
k_down(const f16* __restrict__ As, const f16* __restrict__ Ar,
       const f16* __restrict__ Bs, const f16* __restrict__ Be,
       const float* __restrict__ X, float* __restrict__ out, float* __restrict__ rout)
{
    extern __shared__ char smraw[];
    const uint32_t smu = s2u(smraw);
    const int tid = threadIdx.x;
    const int bn = blockIdx.x * 128;
    const int bm = blockIdx.y * 128;
    const int z = blockIdx.z;

    const f16 *A, *B;
    int rbase = 0;
    if (z == 0) {
        A = As; B = Bs;
    } else {
        const int e = z - 1;
        if (bm >= g_cnt[e]) return;
        rbase = g_base[e];
        A = Ar; B = Be + (size_t)e * 1048576;
    }

    const int lr = tid >> 3;       // 0..31
    const int lc = tid & 7;
    const int coff = lc * 8;

    const f16 *arp[4], *brp[4];
    uint32_t dA[4], dB[4];
#pragma unroll
    for (int i = 0; i < 4; i++) {
        const int r = lr + 32 * i;
        arp[i] = A + (size_t)(rbase + bm + r) * 1024 + coff;
        brp[i] = B + (size_t)(bn + r) * 1024 + coff;
        const uint32_t o = (uint32_t)(r * 128 + ((lc ^ (r & 7)) << 4));
        dA[i] = o; dB[i] = 16384u + o;
    }

    const int lane = tid & 31, w = tid >> 5;
    const int m0 = (w & 3) * 32, n0 = (w >> 2) * 64;

    float acc[2][8][4];
#pragma unroll
    for (int mf = 0; mf < 2; mf++)
#pragma unroll
        for (int nf = 0; nf < 8; nf++)
#pragma unroll
            for (int j = 0; j < 4; j++) acc[mf][nf][j] = 0.f;

#pragma unroll
    for (int st = 0; st < 2; st++) {
        const uint32_t sa = smu + st * DN_STG;
        const int kb = st * 64;
#pragma unroll
        for (int i = 0; i < 4; i++) { cp16(sa + dA[i], arp[i] + kb); cp16(sa + dB[i], brp[i] + kb); }
        cp_commit();
    }

    const int ar_ = lane & 15;
    const int ac_ = lane >> 4;
    const int br_ = (lane & 7) + ((lane >> 4) << 3);
    const int bc_ = (lane >> 3) & 1;

    int stw = 2;
    for (int it = 0; it < 16; ++it) {
        if (it + 2 < 16) {
            const uint32_t sa = smu + stw * DN_STG;
            const int kb = (it + 2) * 64;
#pragma unroll
            for (int i = 0; i < 4; i++) { cp16(sa + dA[i], arp[i] + kb); cp16(sa + dB[i], brp[i] + kb); }
            stw = (stw + 1) == 3 ? 0 : stw + 1;
        }
        cp_commit();
        cp_wait2();
        __syncthreads();

        const uint32_t sa = smu + (it % 3) * DN_STG;
        const uint32_t sb = sa + 16384u;
#pragma unroll
        for (int s = 0; s < 4; s++) {
            uint32_t av[2][4], bv[4][4];
#pragma unroll
            for (int mf = 0; mf < 2; mf++) {
                const int r = m0 + mf * 16 + ar_;
                const int c = s * 2 + ac_;
                ldsm4(av[mf], sa + r * 128 + ((c ^ (r & 7)) << 4));
            }
#pragma unroll
            for (int bi = 0; bi < 4; bi++) {
                const int nr = n0 + bi * 16 + br_;
                const int c = s * 2 + bc_;
                ldsm4(bv[bi], sb + nr * 128 + ((c ^ (nr & 7)) << 4));
            }
#pragma unroll
            for (int mf = 0; mf < 2; mf++)
#pragma unroll
                for (int nf = 0; nf < 8; nf++)
                    mma_f16(acc[mf][nf], av[mf], &bv[nf >> 1][(nf & 1) * 2]);
        }
        __syncthreads();
    }

    const int mr = lane >> 2, nc2 = (lane & 3) * 2;
#pragma unroll
    for (int mf = 0; mf < 2; mf++)
#pragma unroll
        for (int nf = 0; nf < 8; nf++)
#pragma unroll
            for (int h = 0; h < 2; h++) {
                const int rl = m0 + mf * 16 + mr + h * 8;
                const int col = bn + n0 + nf * 8 + nc2;
                const float c0 = acc[mf][nf][h * 2], c1 = acc[mf][nf][h * 2 + 1];
                if (z == 0) {
                    const int t = bm + rl;
                    const float2 rv = *reinterpret_cast<const float2*>(X + (size_t)t * 1024 + col);
                    float2 v = make_float2(rv.x + c0, rv.y + c1);
                    *reinterpret_cast<float2*>(out + (size_t)t * 1024 + col) = v;
                } else {
                    const int orow = rbase + bm + rl;
                    float2 v = make_float2(c0, c1);
                    *reinterpret_cast<float2*>(rout + (size_t)orow * 1024 + col) = v;
                }
            }
}

// ---------------------------------------------------------------------------
// combine: out[t] += w1*rout[slot1] + w2*rout[slot2]
// ---------------------------------------------------------------------------
__global__ void k_combine(float* __restrict__ out) {
    const int t = blockIdx.x;
    const int e1 = g_sel_e[t * 2],     p1 = g_sel_p[t * 2];
    const int e2 = g_sel_e[t * 2 + 1], p2 = g_sel_p[t * 2 + 1];
    const float w1 = g_sel_w[t * 2], w2 = g_sel_w[t * 2 + 1];
    const float* r1 = g_rout + (size_t)(g_base[e1] + p1) * 1024;
    const float* r2 = g_rout + (size_t)(g_base[e2] + p2) * 1024;
    float* o = out + (size_t)t * 1024;
#pragma unroll
    for (int k = 0; k < 2; k++) {
        const int j = (threadIdx.x + k * 128) * 4;
        const float4 a = *(const float4*)(r1 + j);
        const float4 b = *(const float4*)(r2 + j);
        float4 v = *(float4*)(o + j);
        v.x += w1 * a.x + w2 * b.x; v.y += w1 * a.y + w2 * b.y;
        v.z += w1 * a.z + w2 * b.z; v.w += w1 * a.w + w2 * b.w;
        *(float4*)(o + j) = v;
    }
}

// ---------------------------------------------------------------------------
// launch
// ---------------------------------------------------------------------------
extern "C" void kernel_launch(void* const* d_in, const int* in_sizes, int n_in,
                              void* d_out, int out_size)
{
    const float* X  = (const float*)d_in[0];
    const float* RW = (const float*)d_in[1];
    const float* SG = (const float*)d_in[2];
    const float* SU = (const float*)d_in[3];
    const float* SD = (const float*)d_in[4];
    const float* EG = (const float*)d_in[5];
    const float* EU = (const float*)d_in[6];
    const float* ED = (const float*)d_in[7];
    float* out = (float*)d_out;

    static bool once = false;
    if (!once) {
        cudaFuncSetAttribute(k_gateup, cudaFuncAttributeMaxDynamicSharedMemorySize, GU_SMEM);
        cudaFuncSetAttribute(k_down,   cudaFuncAttributeMaxDynamicSharedMemorySize, DN_SMEM);
        once = true;
    }

    f16 *xc, *wsg, *wsu, *wsd, *weg, *weu, *wed, *hids, *hidr;
    float *rout;
    cudaGetSymbolAddress((void**)&xc,   g_xc);
    cudaGetSymbolAddress((void**)&wsg,  g_wsg);
    cudaGetSymbolAddress((void**)&wsu,  g_wsu);
    cudaGetSymbolAddress((void**)&wsd,  g_wsd);
    cudaGetSymbolAddress((void**)&weg,  g_weg);
    cudaGetSymbolAddress((void**)&weu,  g_weu);
    cudaGetSymbolAddress((void**)&wed,  g_wed);
    cudaGetSymbolAddress((void**)&hids, g_hid_s);
    cudaGetSymbolAddress((void**)&hidr, g_hid_r);
    cudaGetSymbolAddress((void**)&rout, g_rout);

    k_init<<<1, 32>>>();
    k_router<<<1024, 128>>>(X, RW);
    k_offsets<<<1, 32>>>();
    k_convx<<<2048, 256>>>(X);
    k_convw<<<dim3(16, 16, 27), 256>>>(SG, SU, SD, EG, EU, ED,
                                       wsg, wsu, wsd, weg, weu, wed);

    k_gateup<<<dim3(8, 32, 9), 512, GU_SMEM>>>(xc, wsg, wsu, weg, weu, hids, hidr);
    k_down  <<<dim3(8, 32, 9), 256, DN_SMEM>>>(hids, hidr, wsd, wed, X, out, rout);

    k_combine<<<T_TOK, 128>>>(out);
}